// round 11
// baseline (speedup 1.0000x reference)
#include <cuda_runtime.h>
#include <math.h>
#include <stdint.h>

#define T_DIM  2048
#define B_DIM  8
#define IN_D   512
#define DV     512
#define DK     128
#define CHK    128
#define NCH    16
#define EPSV   1e-8f

#define BM  128
#define BN  128
#define BKT 16
#define NSTG 4
#define SZ   2176
#define DYN_SMEM (NSTG * SZ * 2 * 4)   // 69632 bytes
#define KCROW 16
#define KRROW 136

// ---------------- scratch ----------------
__device__ uint32_t g_wt [(DV + 3*DK) * IN_D];
__device__ uint32_t g_v  [T_DIM*B_DIM*DV];
__device__ float    g_k  [T_DIM*B_DIM*DK];
__device__ float    g_q  [T_DIM*B_DIM*DK];
__device__ float    g_a  [T_DIM*B_DIM*DK];
__device__ uint32_t g_qt [NCH*B_DIM*CHK*DK];
__device__ uint32_t g_kt [NCH*B_DIM*CHK*DK];
__device__ float    g_cpl[NCH*B_DIM*DK];
__device__ uint32_t g_Am [NCH*B_DIM*CHK*CHK];
__device__ float    g_U  [NCH*B_DIM*DV*DK];
__device__ uint32_t g_S  [NCH*B_DIM*DV*DK];

__device__ __forceinline__ uint32_t f2tf32(float f) {
    uint32_t u;
    asm("cvt.rna.tf32.f32 %0, %1;" : "=r"(u) : "f"(f));
    return u;
}

__device__ __forceinline__ void mma_tf32(float* d, const uint32_t* a, const uint32_t* b) {
    asm volatile(
        "mma.sync.aligned.m16n8k8.row.col.f32.tf32.tf32.f32 "
        "{%0,%1,%2,%3}, {%4,%5,%6,%7}, {%8,%9}, {%0,%1,%2,%3};"
        : "+f"(d[0]), "+f"(d[1]), "+f"(d[2]), "+f"(d[3])
        : "r"(a[0]), "r"(a[1]), "r"(a[2]), "r"(a[3]),
          "r"(b[0]), "r"(b[1]));
}

__device__ __forceinline__ void cp16(uint32_t* smem, const uint32_t* g) {
    uint32_t s = (uint32_t)__cvta_generic_to_shared(smem);
    asm volatile("cp.async.cg.shared.global [%0], [%1], 16;" :: "r"(s), "l"(g));
}
__device__ __forceinline__ void cp_commit() { asm volatile("cp.async.commit_group;"); }
__device__ __forceinline__ void cp_wait2()  { asm volatile("cp.async.wait_group 2;"); }

__device__ __forceinline__ int kc_off(int m, int kk) {
    return m * KCROW + (kk ^ (((m >> 1) & 3) << 2));
}

// ---------------- fragment compute on one stage ----------------
template<bool AKC, bool BKC>
__device__ __forceinline__ void compute_stage(
    const uint32_t* sa, const uint32_t* sb,
    int wm0, int wn0, int gid, int tig, float acc[4][4][4])
{
#pragma unroll
    for (int ks = 0; ks < BKT; ks += 8) {
        uint32_t af[4][4], bf2[4][2];
#pragma unroll
        for (int mi = 0; mi < 4; mi++) {
            int mr = wm0 + mi * 16 + gid;
            if (AKC) {
                int fm = ((mr >> 1) & 3) << 2;
                const uint32_t* r0p = sa + mr * KCROW;
                const uint32_t* r1p = sa + (mr + 8) * KCROW;
                af[mi][0] = r0p[(ks + tig) ^ fm];
                af[mi][1] = r1p[(ks + tig) ^ fm];
                af[mi][2] = r0p[(ks + tig + 4) ^ fm];
                af[mi][3] = r1p[(ks + tig + 4) ^ fm];
            } else {
                af[mi][0] = sa[(ks + tig) * KRROW + mr];
                af[mi][1] = sa[(ks + tig) * KRROW + mr + 8];
                af[mi][2] = sa[(ks + tig + 4) * KRROW + mr];
                af[mi][3] = sa[(ks + tig + 4) * KRROW + mr + 8];
            }
        }
#pragma unroll
        for (int ni = 0; ni < 4; ni++) {
            int nc = wn0 + ni * 8 + gid;
            if (BKC) {
                int fn = ((nc >> 1) & 3) << 2;
                const uint32_t* rp = sb + nc * KCROW;
                bf2[ni][0] = rp[(ks + tig) ^ fn];
                bf2[ni][1] = rp[(ks + tig + 4) ^ fn];
            } else {
                bf2[ni][0] = sb[(ks + tig) * KRROW + nc];
                bf2[ni][1] = sb[(ks + tig + 4) * KRROW + nc];
            }
        }
#pragma unroll
        for (int mi = 0; mi < 4; mi++)
#pragma unroll
            for (int ni = 0; ni < 4; ni++)
                mma_tf32(acc[mi][ni], af[mi], bf2[ni]);
    }
}

// ---------------- 4-stage cp.async pipeline ----------------
template<long ASM, long ASK, long BSK, long BSN, int KK>
__device__ __forceinline__ void pipe(
    const uint32_t* __restrict__ Ap, const uint32_t* __restrict__ Bp,
    int m0, int n0, int tid, float acc[4][4][4],
    uint32_t* SA, uint32_t* SB)
{
    constexpr bool AKC = (ASK == 1);
    constexpr bool BKC = (BSK == 1);
    constexpr int NKI = KK / BKT;
    static_assert(NKI >= 3, "pipeline needs >=3 k-iters");

    int warp = tid >> 5, lane = tid & 31;
    int wm0 = (warp & 1) * 64;
    int wn0 = (warp >> 1) * 32;
    int gid = lane >> 2, tig = lane & 3;

    auto issueA = [&](uint32_t* dst, int k0) {
#pragma unroll
        for (int i = 0; i < 2; i++) {
            int q = tid + i * 256;
            if (AKC) {
                int m = q >> 2, c = q & 3;
                cp16(dst + kc_off(m, c << 2), Ap + (long)(m0 + m) * ASM + (k0 + (c << 2)));
            } else {
                int k = q >> 5, m4 = (q & 31) << 2;
                cp16(dst + k * KRROW + m4, Ap + (long)(m0 + m4) * ASM + (long)(k0 + k) * ASK);
            }
        }
    };
    auto issueB = [&](uint32_t* dst, int k0) {
#pragma unroll
        for (int i = 0; i < 2; i++) {
            int q = tid + i * 256;
            if (BKC) {
                int n = q >> 2, c = q & 3;
                cp16(dst + kc_off(n, c << 2), Bp + (long)(n0 + n) * BSN + (k0 + (c << 2)));
            } else {
                int k = q >> 5, n4 = (q & 31) << 2;
                cp16(dst + k * KRROW + n4, Bp + (long)(k0 + k) * BSK + (long)(n0 + n4) * BSN);
            }
        }
    };

    __syncthreads();

    issueA(SA, 0);            issueB(SB, 0);            cp_commit();
    issueA(SA + SZ, BKT);     issueB(SB + SZ, BKT);     cp_commit();
    issueA(SA + 2*SZ, 2*BKT); issueB(SB + 2*SZ, 2*BKT); cp_commit();

    int stage = 0;
    for (int i = 0; i < NKI; i++) {
        cp_wait2();
        __syncthreads();
        {
            int s3 = stage + 3; if (s3 >= NSTG) s3 -= NSTG;
            if (i + 3 < NKI) {
                issueA(SA + s3 * SZ, (i + 3) * BKT);
                issueB(SB + s3 * SZ, (i + 3) * BKT);
            }
            cp_commit();
        }
        compute_stage<AKC, BKC>(SA + stage * SZ, SB + stage * SZ, wm0, wn0, gid, tig, acc);
        stage++; if (stage == NSTG) stage = 0;
    }
}

// ---------------- shared epilogue ----------------
template<long CSM, bool CAUSAL, bool OUT_TF32, bool ACC>
__device__ __forceinline__ void epilogue(float acc[4][4][4], void* Cbase,
                                         int m0, int n0, int tid) {
    int warp = tid >> 5, lane = tid & 31;
    int wm0 = (warp & 1) * 64, wn0 = (warp >> 1) * 32;
    int gid = lane >> 2, tig = lane & 3;
    float*    Cf = (float*)Cbase;
    uint32_t* Cu = (uint32_t*)Cbase;
#pragma unroll
    for (int mi = 0; mi < 4; mi++) {
        int r0 = m0 + wm0 + mi * 16 + gid;
#pragma unroll
        for (int ni = 0; ni < 4; ni++) {
            int c0 = n0 + wn0 + ni * 8 + 2 * tig;
#pragma unroll
            for (int f = 0; f < 4; f++) {
                int row = r0 + (f >> 1) * 8;
                int col = c0 + (f & 1);
                float v = acc[mi][ni][f];
                if (CAUSAL && col > row) v = 0.f;
                long idx = (long)row * CSM + col;
                if (OUT_TF32) Cu[idx] = f2tf32(v);
                else if (ACC)  Cf[idx] += v;
                else           Cf[idx] = v;
            }
        }
    }
}

// ---------------- A = q~ @ k~^T (causal) ----------------
__global__ __launch_bounds__(256, 2) void gemm_A(
    const uint32_t* __restrict__ qt, const uint32_t* __restrict__ kt,
    uint32_t* __restrict__ Am)
{
    extern __shared__ uint32_t dynsm[];
    uint32_t* SA = dynsm;
    uint32_t* SB = dynsm + NSTG * SZ;
    int bx = blockIdx.x, tid = threadIdx.x;

    float acc[4][4][4];
#pragma unroll
    for (int i = 0; i < 4; i++)
#pragma unroll
        for (int j = 0; j < 4; j++)
#pragma unroll
            for (int f = 0; f < 4; f++) acc[i][j][f] = 0.f;

    pipe<DK, 1, 1, DK, DK>(qt + (long)bx * CHK * DK, kt + (long)bx * CHK * DK,
                           0, 0, tid, acc, SA, SB);
    epilogue<CHK, true, true, false>(acc, Am + (long)bx * CHK * CHK, 0, 0, tid);
}

// ---------------- U = V^T @ k~ ----------------
__global__ __launch_bounds__(256, 2) void gemm_U(
    const uint32_t* __restrict__ kt, const uint32_t* __restrict__ v,
    float* __restrict__ U)
{
    extern __shared__ uint32_t dynsm[];
    uint32_t* SA = dynsm;
    uint32_t* SB = dynsm + NSTG * SZ;
    int q = blockIdx.x, tid = threadIdx.x;
    int mt = q & 3, zz = q >> 2;
    int cz = zz >> 3, bb = zz & 7;

    float acc[4][4][4];
#pragma unroll
    for (int i = 0; i < 4; i++)
#pragma unroll
        for (int j = 0; j < 4; j++)
#pragma unroll
            for (int f = 0; f < 4; f++) acc[i][j][f] = 0.f;

    pipe<1, (long)B_DIM * DV, DK, 1, CHK>(
        v + (long)cz * CHK * B_DIM * DV + (long)bb * DV,
        kt + (long)zz * CHK * DK, mt * BM, 0, tid, acc, SA, SB);
    epilogue<DK, false, false, false>(acc, U + (long)zz * DV * DK, mt * BM, 0, tid);
}

// ---------------- Y1: y = A@V ----------------
__global__ __launch_bounds__(256, 2) void gemm_Y1(
    const uint32_t* __restrict__ Am, const uint32_t* __restrict__ v,
    float* __restrict__ y)
{
    extern __shared__ uint32_t dynsm[];
    uint32_t* SA = dynsm;
    uint32_t* SB = dynsm + NSTG * SZ;

    int bz = blockIdx.z;
    int cz = bz >> 3, bb = bz & 7;
    int n0 = blockIdx.x * BN;
    int tid = threadIdx.x;

    float acc[4][4][4];
#pragma unroll
    for (int i = 0; i < 4; i++)
#pragma unroll
        for (int j = 0; j < 4; j++)
#pragma unroll
            for (int f = 0; f < 4; f++) acc[i][j][f] = 0.f;

    pipe<CHK, 1, (long)B_DIM * DV, 1, CHK>(
        Am + (long)bz * CHK * CHK,
        v + (long)cz * CHK * B_DIM * DV + (long)bb * DV,
        0, n0, tid, acc, SA, SB);

    epilogue<(long)B_DIM * DV, false, false, false>(
        acc, y + (long)cz * CHK * B_DIM * DV + (long)bb * DV, 0, n0, tid);
}

// ---------------- Y2: y += q~ @ S^T ----------------
__global__ __launch_bounds__(256, 2) void gemm_Y2(
    const uint32_t* __restrict__ qt, const uint32_t* __restrict__ S,
    float* __restrict__ y)
{
    extern __shared__ uint32_t dynsm[];
    uint32_t* SA = dynsm;
    uint32_t* SB = dynsm + NSTG * SZ;

    int bz = blockIdx.z;
    int cz = bz >> 3, bb = bz & 7;
    int n0 = blockIdx.x * BN;
    int tid = threadIdx.x;

    float acc[4][4][4];
#pragma unroll
    for (int i = 0; i < 4; i++)
#pragma unroll
        for (int j = 0; j < 4; j++)
#pragma unroll
            for (int f = 0; f < 4; f++) acc[i][j][f] = 0.f;

    pipe<DK, 1, 1, DK, DK>(
        qt + (long)bz * CHK * DK,
        S + (long)bz * DV * DK,
        0, n0, tid, acc, SA, SB);

    epilogue<(long)B_DIM * DV, false, false, true>(
        acc, y + (long)cz * CHK * B_DIM * DV + (long)bb * DV, 0, n0, tid);
}

// ---------------- projection kernel ----------------
struct ProjArgs {
    const float* X;
    const uint32_t* Bm[7];
    const float* biasm[7];
    void* Cm[7];
    int noff[7]; int cs[7]; int otf[7];
    int base;
};

__global__ __launch_bounds__(256, 2) void proj_kernel(ProjArgs g) {
    extern __shared__ uint32_t dynsm[];
    uint32_t* SA = dynsm;
    uint32_t* SB = dynsm + NSTG * SZ;

    int sx = blockIdx.x + g.base;
    int m0 = blockIdx.y * BM;
    int n0 = g.noff[sx];
    int tid = threadIdx.x;
    constexpr int NKI = IN_D / BKT;   // 32

    int warp = tid >> 5, lane = tid & 31;
    int wm0 = (warp & 1) * 64, wn0 = (warp >> 1) * 32;
    int gid = lane >> 2, tig = lane & 3;

    const float* __restrict__ X = g.X;
    const uint32_t* __restrict__ W = g.Bm[sx];

    float acc[4][4][4];
#pragma unroll
    for (int i = 0; i < 4; i++)
#pragma unroll
        for (int j = 0; j < 4; j++)
#pragma unroll
            for (int f = 0; f < 4; f++) acc[i][j][f] = 0.f;

    float4 ra[2];
    auto ldgA = [&](int k0) {
#pragma unroll
        for (int i = 0; i < 2; i++) {
            int q = tid + i * 256;
            int m = q >> 2, c = q & 3;
            ra[i] = *reinterpret_cast<const float4*>(X + (long)(m0 + m) * IN_D + k0 + (c << 2));
        }
    };
    auto stsA = [&](uint32_t* dst) {
#pragma unroll
        for (int i = 0; i < 2; i++) {
            int q = tid + i * 256;
            int m = q >> 2, c = q & 3;
            uint4 o;
            o.x = f2tf32(ra[i].x); o.y = f2tf32(ra[i].y);
            o.z = f2tf32(ra[i].z); o.w = f2tf32(ra[i].w);
            *reinterpret_cast<uint4*>(dst + kc_off(m, c << 2)) = o;
        }
    };
    auto issueB = [&](uint32_t* dst, int k0) {
#pragma unroll
        for (int i = 0; i < 2; i++) {
            int q = tid + i * 256;
            int n = q >> 2, c = q & 3;
            cp16(dst + kc_off(n, c << 2), W + (long)(n0 + n) * IN_D + (k0 + (c << 2)));
        }
    };

    ldgA(0);
    stsA(SA);
    ldgA(BKT);
    issueB(SB, 0);            cp_commit();
    issueB(SB + SZ, BKT);     cp_commit();
    issueB(SB + 2*SZ, 2*BKT); cp_commit();

    int stage = 0;
    for (int i = 0; i < NKI; i++) {
        cp_wait2();
        __syncthreads();
        {
            int s1 = stage + 1; if (s1 >= NSTG) s1 -= NSTG;
            int s3 = stage + 3; if (s3 >= NSTG) s3 -= NSTG;
            if (i + 3 < NKI) issueB(SB + s3 * SZ, (i + 3) * BKT);
            cp_commit();
            if (i + 1 < NKI) stsA(SA + s1 * SZ);
            if (i + 2 < NKI) ldgA((i + 2) * BKT);
        }
        compute_stage<true, true>(SA + stage * SZ, SB + stage * SZ, wm0, wn0, gid, tig, acc);
        stage++; if (stage == NSTG) stage = 0;
    }

    const float* bias = g.biasm[sx];
    int cs = g.cs[sx];
    int otf = g.otf[sx];
#pragma unroll
    for (int mi = 0; mi < 4; mi++) {
        int r0 = m0 + wm0 + mi * 16 + gid;
#pragma unroll
        for (int ni = 0; ni < 4; ni++) {
            int c0 = n0 + wn0 + ni * 8 + 2 * tig;
#pragma unroll
            for (int f = 0; f < 4; f++) {
                int row = r0 + (f >> 1) * 8;
                int col = c0 + (f & 1);
                float v = acc[mi][ni][f] + bias[col];
                long idx = (long)row * cs + col;
                if (otf) ((uint32_t*)g.Cm[sx])[idx] = f2tf32(v);
                else     ((float*)g.Cm[sx])[idx]    = v;
            }
        }
    }
}

// ---------------- weight-only fp32 -> tf32 conversion ----------------
#define NW4 ((DV + 3*DK) * IN_D / 4)
__global__ void conv_w(const float4* __restrict__ wv, const float4* __restrict__ wk,
                       const float4* __restrict__ wq, const float4* __restrict__ wa)
{
    long i = (long)blockIdx.x * blockDim.x + threadIdx.x;
    if (i >= NW4) return;
    const long NWV4 = DV * IN_D / 4, NWK4 = DK * IN_D / 4;
    float4 s;
    long j = i;
    if (j < NWV4) s = wv[j];
    else { j -= NWV4;
        if (j < NWK4) s = wk[j];
        else { j -= NWK4;
            if (j < NWK4) s = wq[j];
            else s = wa[j - NWK4];
        }
    }
    uint4 o;
    o.x = f2tf32(s.x); o.y = f2tf32(s.y); o.z = f2tf32(s.z); o.w = f2tf32(s.w);
    ((uint4*)g_wt)[i] = o;
}

// ---------------- parallel decay prep (MUFU sigmoid) ----------------
#define NSEG 8
#define SEGL (CHK / NSEG)   // 16
__global__ __launch_bounds__(1024) void prep_kernel() {
    int cb = blockIdx.x;
    int c = cb >> 3, b = cb & 7;
    int tid = threadIdx.x;
    int n = tid & 127, seg = tid >> 7;

    __shared__ float sprod[NSEG][DK];

    int t0 = seg * SEGL;
    float sg[SEGL];
    float p = 1.f;
#pragma unroll
    for (int i = 0; i < SEGL; i++) {
        long row = (long)(c * CHK + t0 + i) * B_DIM + b;
        float av = g_a[row * DK + n];
        float s = fmaxf(__fdividef(1.f, 1.f + __expf(-av)), EPSV);
        sg[i] = s;
        p *= s;
    }
    sprod[seg][n] = p;
    __syncthreads();

    float cp = 1.f;
#pragma unroll
    for (int j = 0; j < NSEG - 1; j++)
        if (j < seg) cp *= sprod[j][n];

    long base_o = ((long)cb * CHK) * DK + n;
#pragma unroll
    for (int i = 0; i < SEGL; i++) {
        int t = t0 + i;
        long row = (long)(c * CHK + t) * B_DIM + b;
        cp *= sg[i];
        g_qt[base_o + (long)t * DK] = f2tf32(g_q[row * DK + n] * cp);
        g_kt[base_o + (long)t * DK] = f2tf32(g_k[row * DK + n] / (cp + EPSV));
    }
    if (seg == NSEG - 1)
        g_cpl[(long)cb * DK + n] = cp;
}

// ---------------- inter-chunk state scan ----------------
__global__ void scan_kernel() {
    int id = blockIdx.x * blockDim.x + threadIdx.x;
    int n = id & (DK - 1);
    int d = (id >> 7) & (DV - 1);
    int b = id >> 16;
    float s = 0.f;
#pragma unroll
    for (int c = 0; c < NCH; c++) {
        long off = (((long)c * B_DIM + b) * DV + d) * DK + n;
        g_S[off] = f2tf32(s);
        float cl = g_cpl[((long)c * B_DIM + b) * DK + n];
        s = cl * (s + g_U[off]);
    }
}

// ---------------- host launcher ----------------
extern "C" void kernel_launch(void* const* d_in, const int* in_sizes, int n_in,
                              void* d_out, int out_size) {
    const float* x  = (const float*)d_in[0];
    const float* Wv = (const float*)d_in[1];
    const float* bv = (const float*)d_in[2];
    const float* Wk = (const float*)d_in[3];
    const float* bk = (const float*)d_in[4];
    const float* Wq = (const float*)d_in[5];
    const float* bq = (const float*)d_in[6];
    const float* Wa = (const float*)d_in[7];
    const float* ba = (const float*)d_in[8];
    float* y = (float*)d_out;
    (void)in_sizes; (void)n_in; (void)out_size;

    uint32_t *pwt, *pv, *pqt, *pkt, *pA, *pS;
    float *pk, *pq, *pa, *pU;
    cudaGetSymbolAddress((void**)&pwt, g_wt);
    cudaGetSymbolAddress((void**)&pv,  g_v);
    cudaGetSymbolAddress((void**)&pk,  g_k);
    cudaGetSymbolAddress((void**)&pq,  g_q);
    cudaGetSymbolAddress((void**)&pa,  g_a);
    cudaGetSymbolAddress((void**)&pqt, g_qt);
    cudaGetSymbolAddress((void**)&pkt, g_kt);
    cudaGetSymbolAddress((void**)&pA,  g_Am);
    cudaGetSymbolAddress((void**)&pU,  g_U);
    cudaGetSymbolAddress((void**)&pS,  g_S);

    static cudaStream_t s2 = 0;
    static cudaEvent_t evW = 0, evP = 0, evV = 0, evS = 0;
    static bool inited = false;
    if (!inited) {
        cudaStreamCreateWithFlags(&s2, cudaStreamNonBlocking);
        cudaEventCreateWithFlags(&evW, cudaEventDisableTiming);
        cudaEventCreateWithFlags(&evP, cudaEventDisableTiming);
        cudaEventCreateWithFlags(&evV, cudaEventDisableTiming);
        cudaEventCreateWithFlags(&evS, cudaEventDisableTiming);
        cudaFuncSetAttribute(proj_kernel, cudaFuncAttributeMaxDynamicSharedMemorySize, DYN_SMEM);
        cudaFuncSetAttribute(gemm_A, cudaFuncAttributeMaxDynamicSharedMemorySize, DYN_SMEM);
        cudaFuncSetAttribute(gemm_U, cudaFuncAttributeMaxDynamicSharedMemorySize, DYN_SMEM);
        cudaFuncSetAttribute(gemm_Y1, cudaFuncAttributeMaxDynamicSharedMemorySize, DYN_SMEM);
        cudaFuncSetAttribute(gemm_Y2, cudaFuncAttributeMaxDynamicSharedMemorySize, DYN_SMEM);
        inited = true;
    }

    // ---- weight tf32 conversion ----
    conv_w<<<(NW4 + 255) / 256, 256>>>(
        (const float4*)Wv, (const float4*)Wk, (const float4*)Wq, (const float4*)Wa);

    // fork
    cudaEventRecord(evW, 0);
    cudaStreamWaitEvent(s2, evW, 0);

    ProjArgs gp;
    {
        gp.X = x;
        const long NWV4 = DV * IN_D / 4, NWK4 = DK * IN_D / 4;
        const uint32_t* wv_t = pwt;
        const uint32_t* wk_t = pwt + NWV4 * 4;
        const uint32_t* wq_t = pwt + (NWV4 + NWK4) * 4;
        const uint32_t* wa_t = pwt + (NWV4 + 2 * NWK4) * 4;
        const uint32_t* Bm[7]    = {wk_t, wq_t, wa_t, wv_t, wv_t, wv_t, wv_t};
        const float*    biasm[7] = {bk, bq, ba, bv, bv, bv, bv};
        void*           Cm[7]    = {pk, pq, pa, pv, pv, pv, pv};
        int             noff[7]  = {0, 0, 0, 0, 128, 256, 384};
        int             cs[7]    = {DK, DK, DK, DV, DV, DV, DV};
        int             otf[7]   = {0, 0, 0, 1, 1, 1, 1};
        for (int i = 0; i < 7; i++) {
            gp.Bm[i] = Bm[i]; gp.biasm[i] = biasm[i]; gp.Cm[i] = Cm[i];
            gp.noff[i] = noff[i]; gp.cs[i] = cs[i]; gp.otf[i] = otf[i];
        }
    }

    // stream0: k,q,a projections -> prep -> gemm_A -> Y1 -> Y2
    gp.base = 0;
    proj_kernel<<<dim3(3, T_DIM * B_DIM / BM, 1), 256, DYN_SMEM, 0>>>(gp);
    // s2: v projection
    ProjArgs gpv = gp; gpv.base = 3;
    proj_kernel<<<dim3(4, T_DIM * B_DIM / BM, 1), 256, DYN_SMEM, s2>>>(gpv);
    cudaEventRecord(evV, s2);

    prep_kernel<<<NCH * B_DIM, NSEG * DK, 0, 0>>>();
    cudaEventRecord(evP, 0);
    gemm_A<<<NCH * B_DIM, 256, DYN_SMEM, 0>>>(pqt, pkt, pA);

    // s2: gemm_U (needs kt from prep + v local) -> scan
    cudaStreamWaitEvent(s2, evP, 0);
    gemm_U<<<NCH * B_DIM * (DV / BM), 256, DYN_SMEM, s2>>>(pkt, pv, pU);
    scan_kernel<<<(B_DIM * DV * DK) / 256, 256, 0, s2>>>();
    cudaEventRecord(evS, s2);

    // stream0: Y1 = A@V (needs Am local + v from s2)
    cudaStreamWaitEvent(0, evV, 0);
    gemm_Y1<<<dim3(DV / BN, 1, NCH * B_DIM), 256, DYN_SMEM, 0>>>(pA, pv, y);
    // Y2 += q~@S^T (needs S from scan)
    cudaStreamWaitEvent(0, evS, 0);
    gemm_Y2<<<dim3(DV / BN, 1, NCH * B_DIM), 256, DYN_SMEM, 0>>>(pqt, pS, y);
}

// round 12
// speedup vs baseline: 1.0742x; 1.0742x over previous
#include <cuda_runtime.h>
#include <math.h>
#include <stdint.h>

#define T_DIM  2048
#define B_DIM  8
#define IN_D   512
#define DV     512
#define DK     128
#define CHK    128
#define NCH    16
#define EPSV   1e-8f

#define BM  128
#define BN  128
#define BKT 16
#define NSTG 4
#define SZ   2176
#define DYN_SMEM (NSTG * SZ * 2 * 4)   // 69632 bytes
#define KCROW 16
#define KRROW 136

// ---------------- scratch ----------------
__device__ uint32_t g_wt [(DV + 3*DK) * IN_D];
__device__ uint32_t g_v  [T_DIM*B_DIM*DV];
__device__ float    g_k  [T_DIM*B_DIM*DK];
__device__ float    g_q  [T_DIM*B_DIM*DK];
__device__ float    g_a  [T_DIM*B_DIM*DK];
__device__ uint32_t g_qt [NCH*B_DIM*CHK*DK];
__device__ uint32_t g_kt [NCH*B_DIM*CHK*DK];
__device__ float    g_cpl[NCH*B_DIM*DK];
__device__ uint32_t g_Am [NCH*B_DIM*CHK*CHK];
__device__ float    g_U  [NCH*B_DIM*DV*DK];
__device__ uint32_t g_S  [NCH*B_DIM*DV*DK];

__device__ __forceinline__ uint32_t f2tf32(float f) {
    uint32_t u;
    asm("cvt.rna.tf32.f32 %0, %1;" : "=r"(u) : "f"(f));
    return u;
}

__device__ __forceinline__ void mma_tf32(float* d, const uint32_t* a, const uint32_t* b) {
    asm volatile(
        "mma.sync.aligned.m16n8k8.row.col.f32.tf32.tf32.f32 "
        "{%0,%1,%2,%3}, {%4,%5,%6,%7}, {%8,%9}, {%0,%1,%2,%3};"
        : "+f"(d[0]), "+f"(d[1]), "+f"(d[2]), "+f"(d[3])
        : "r"(a[0]), "r"(a[1]), "r"(a[2]), "r"(a[3]),
          "r"(b[0]), "r"(b[1]));
}

__device__ __forceinline__ void cp16(uint32_t* smem, const uint32_t* g) {
    uint32_t s = (uint32_t)__cvta_generic_to_shared(smem);
    asm volatile("cp.async.cg.shared.global [%0], [%1], 16;" :: "r"(s), "l"(g));
}
__device__ __forceinline__ void cp_commit() { asm volatile("cp.async.commit_group;"); }
__device__ __forceinline__ void cp_wait2()  { asm volatile("cp.async.wait_group 2;"); }

__device__ __forceinline__ int kc_off(int m, int kk) {
    return m * KCROW + (kk ^ (((m >> 1) & 3) << 2));
}

// ---------------- fragment compute on one stage ----------------
template<bool AKC, bool BKC>
__device__ __forceinline__ void compute_stage(
    const uint32_t* sa, const uint32_t* sb,
    int wm0, int wn0, int gid, int tig, float acc[4][4][4])
{
#pragma unroll
    for (int ks = 0; ks < BKT; ks += 8) {
        uint32_t af[4][4], bf2[4][2];
#pragma unroll
        for (int mi = 0; mi < 4; mi++) {
            int mr = wm0 + mi * 16 + gid;
            if (AKC) {
                int fm = ((mr >> 1) & 3) << 2;
                const uint32_t* r0p = sa + mr * KCROW;
                const uint32_t* r1p = sa + (mr + 8) * KCROW;
                af[mi][0] = r0p[(ks + tig) ^ fm];
                af[mi][1] = r1p[(ks + tig) ^ fm];
                af[mi][2] = r0p[(ks + tig + 4) ^ fm];
                af[mi][3] = r1p[(ks + tig + 4) ^ fm];
            } else {
                af[mi][0] = sa[(ks + tig) * KRROW + mr];
                af[mi][1] = sa[(ks + tig) * KRROW + mr + 8];
                af[mi][2] = sa[(ks + tig + 4) * KRROW + mr];
                af[mi][3] = sa[(ks + tig + 4) * KRROW + mr + 8];
            }
        }
#pragma unroll
        for (int ni = 0; ni < 4; ni++) {
            int nc = wn0 + ni * 8 + gid;
            if (BKC) {
                int fn = ((nc >> 1) & 3) << 2;
                const uint32_t* rp = sb + nc * KCROW;
                bf2[ni][0] = rp[(ks + tig) ^ fn];
                bf2[ni][1] = rp[(ks + tig + 4) ^ fn];
            } else {
                bf2[ni][0] = sb[(ks + tig) * KRROW + nc];
                bf2[ni][1] = sb[(ks + tig + 4) * KRROW + nc];
            }
        }
#pragma unroll
        for (int mi = 0; mi < 4; mi++)
#pragma unroll
            for (int ni = 0; ni < 4; ni++)
                mma_tf32(acc[mi][ni], af[mi], bf2[ni]);
    }
}

// ---------------- 4-stage cp.async pipeline ----------------
template<long ASM, long ASK, long BSK, long BSN, int KK>
__device__ __forceinline__ void pipe(
    const uint32_t* __restrict__ Ap, const uint32_t* __restrict__ Bp,
    int m0, int n0, int tid, float acc[4][4][4],
    uint32_t* SA, uint32_t* SB)
{
    constexpr bool AKC = (ASK == 1);
    constexpr bool BKC = (BSK == 1);
    constexpr int NKI = KK / BKT;
    static_assert(NKI >= 3, "pipeline needs >=3 k-iters");

    int warp = tid >> 5, lane = tid & 31;
    int wm0 = (warp & 1) * 64;
    int wn0 = (warp >> 1) * 32;
    int gid = lane >> 2, tig = lane & 3;

    auto issueA = [&](uint32_t* dst, int k0) {
#pragma unroll
        for (int i = 0; i < 2; i++) {
            int q = tid + i * 256;
            if (AKC) {
                int m = q >> 2, c = q & 3;
                cp16(dst + kc_off(m, c << 2), Ap + (long)(m0 + m) * ASM + (k0 + (c << 2)));
            } else {
                int k = q >> 5, m4 = (q & 31) << 2;
                cp16(dst + k * KRROW + m4, Ap + (long)(m0 + m4) * ASM + (long)(k0 + k) * ASK);
            }
        }
    };
    auto issueB = [&](uint32_t* dst, int k0) {
#pragma unroll
        for (int i = 0; i < 2; i++) {
            int q = tid + i * 256;
            if (BKC) {
                int n = q >> 2, c = q & 3;
                cp16(dst + kc_off(n, c << 2), Bp + (long)(n0 + n) * BSN + (k0 + (c << 2)));
            } else {
                int k = q >> 5, n4 = (q & 31) << 2;
                cp16(dst + k * KRROW + n4, Bp + (long)(k0 + k) * BSK + (long)(n0 + n4) * BSN);
            }
        }
    };

    __syncthreads();

    issueA(SA, 0);            issueB(SB, 0);            cp_commit();
    issueA(SA + SZ, BKT);     issueB(SB + SZ, BKT);     cp_commit();
    issueA(SA + 2*SZ, 2*BKT); issueB(SB + 2*SZ, 2*BKT); cp_commit();

    int stage = 0;
    for (int i = 0; i < NKI; i++) {
        cp_wait2();
        __syncthreads();
        {
            int s3 = stage + 3; if (s3 >= NSTG) s3 -= NSTG;
            if (i + 3 < NKI) {
                issueA(SA + s3 * SZ, (i + 3) * BKT);
                issueB(SB + s3 * SZ, (i + 3) * BKT);
            }
            cp_commit();
        }
        compute_stage<AKC, BKC>(SA + stage * SZ, SB + stage * SZ, wm0, wn0, gid, tig, acc);
        stage++; if (stage == NSTG) stage = 0;
    }
}

// ---------------- shared epilogue ----------------
template<long CSM, bool CAUSAL, bool OUT_TF32>
__device__ __forceinline__ void epilogue(float acc[4][4][4], void* Cbase,
                                         int m0, int n0, int tid) {
    int warp = tid >> 5, lane = tid & 31;
    int wm0 = (warp & 1) * 64, wn0 = (warp >> 1) * 32;
    int gid = lane >> 2, tig = lane & 3;
    float*    Cf = (float*)Cbase;
    uint32_t* Cu = (uint32_t*)Cbase;
#pragma unroll
    for (int mi = 0; mi < 4; mi++) {
        int r0 = m0 + wm0 + mi * 16 + gid;
#pragma unroll
        for (int ni = 0; ni < 4; ni++) {
            int c0 = n0 + wn0 + ni * 8 + 2 * tig;
#pragma unroll
            for (int f = 0; f < 4; f++) {
                int row = r0 + (f >> 1) * 8;
                int col = c0 + (f & 1);
                float v = acc[mi][ni][f];
                if (CAUSAL && col > row) v = 0.f;
                long idx = (long)row * CSM + col;
                if (OUT_TF32) Cu[idx] = f2tf32(v);
                else          Cf[idx] = v;
            }
        }
    }
}

// ---------------- A = q~ @ k~^T (causal) ----------------
__global__ __launch_bounds__(256, 2) void gemm_A(
    const uint32_t* __restrict__ qt, const uint32_t* __restrict__ kt,
    uint32_t* __restrict__ Am)
{
    extern __shared__ uint32_t dynsm[];
    uint32_t* SA = dynsm;
    uint32_t* SB = dynsm + NSTG * SZ;
    int bx = blockIdx.x, tid = threadIdx.x;

    float acc[4][4][4];
#pragma unroll
    for (int i = 0; i < 4; i++)
#pragma unroll
        for (int j = 0; j < 4; j++)
#pragma unroll
            for (int f = 0; f < 4; f++) acc[i][j][f] = 0.f;

    pipe<DK, 1, 1, DK, DK>(qt + (long)bx * CHK * DK, kt + (long)bx * CHK * DK,
                           0, 0, tid, acc, SA, SB);
    epilogue<CHK, true, true>(acc, Am + (long)bx * CHK * CHK, 0, 0, tid);
}

// ---------------- U = V^T @ k~ ----------------
__global__ __launch_bounds__(256, 2) void gemm_U(
    const uint32_t* __restrict__ kt, const uint32_t* __restrict__ v,
    float* __restrict__ U)
{
    extern __shared__ uint32_t dynsm[];
    uint32_t* SA = dynsm;
    uint32_t* SB = dynsm + NSTG * SZ;
    int q = blockIdx.x, tid = threadIdx.x;
    int mt = q & 3, zz = q >> 2;
    int cz = zz >> 3, bb = zz & 7;

    float acc[4][4][4];
#pragma unroll
    for (int i = 0; i < 4; i++)
#pragma unroll
        for (int j = 0; j < 4; j++)
#pragma unroll
            for (int f = 0; f < 4; f++) acc[i][j][f] = 0.f;

    pipe<1, (long)B_DIM * DV, DK, 1, CHK>(
        v + (long)cz * CHK * B_DIM * DV + (long)bb * DV,
        kt + (long)zz * CHK * DK, mt * BM, 0, tid, acc, SA, SB);
    epilogue<DK, false, false>(acc, U + (long)zz * DV * DK, mt * BM, 0, tid);
}

// ---------------- fused Y: y = A@V + q~@S^T ----------------
__global__ __launch_bounds__(256, 2) void gemm_Y(
    const uint32_t* __restrict__ Am, const uint32_t* __restrict__ v,
    float* __restrict__ y, const uint32_t* __restrict__ qt,
    const uint32_t* __restrict__ S)
{
    extern __shared__ uint32_t dynsm[];
    uint32_t* SA = dynsm;
    uint32_t* SB = dynsm + NSTG * SZ;

    int bz = blockIdx.z;
    int cz = bz >> 3, bb = bz & 7;
    int n0 = blockIdx.x * BN;
    int tid = threadIdx.x;

    float acc[4][4][4];
#pragma unroll
    for (int i = 0; i < 4; i++)
#pragma unroll
        for (int j = 0; j < 4; j++)
#pragma unroll
            for (int f = 0; f < 4; f++) acc[i][j][f] = 0.f;

    pipe<CHK, 1, (long)B_DIM * DV, 1, CHK>(
        Am + (long)bz * CHK * CHK,
        v + (long)cz * CHK * B_DIM * DV + (long)bb * DV,
        0, n0, tid, acc, SA, SB);
    pipe<DK, 1, 1, DK, DK>(
        qt + (long)bz * CHK * DK,
        S + (long)bz * DV * DK,
        0, n0, tid, acc, SA, SB);

    epilogue<(long)B_DIM * DV, false, false>(
        acc, y + (long)cz * CHK * B_DIM * DV + (long)bb * DV, 0, n0, tid);
}

// ---------------- projection kernel ----------------
struct ProjArgs {
    const float* X;
    const uint32_t* Bm[7];
    const float* biasm[7];
    void* Cm[7];
    int noff[7]; int cs[7]; int otf[7];
    int base;
};

__global__ __launch_bounds__(256, 2) void proj_kernel(ProjArgs g) {
    extern __shared__ uint32_t dynsm[];
    uint32_t* SA = dynsm;
    uint32_t* SB = dynsm + NSTG * SZ;

    int sx = blockIdx.x + g.base;
    int m0 = blockIdx.y * BM;
    int n0 = g.noff[sx];
    int tid = threadIdx.x;
    constexpr int NKI = IN_D / BKT;   // 32

    int warp = tid >> 5, lane = tid & 31;
    int wm0 = (warp & 1) * 64, wn0 = (warp >> 1) * 32;
    int gid = lane >> 2, tig = lane & 3;

    const float* __restrict__ X = g.X;
    const uint32_t* __restrict__ W = g.Bm[sx];

    float acc[4][4][4];
#pragma unroll
    for (int i = 0; i < 4; i++)
#pragma unroll
        for (int j = 0; j < 4; j++)
#pragma unroll
            for (int f = 0; f < 4; f++) acc[i][j][f] = 0.f;

    float4 ra[2];
    auto ldgA = [&](int k0) {
#pragma unroll
        for (int i = 0; i < 2; i++) {
            int q = tid + i * 256;
            int m = q >> 2, c = q & 3;
            ra[i] = *reinterpret_cast<const float4*>(X + (long)(m0 + m) * IN_D + k0 + (c << 2));
        }
    };
    auto stsA = [&](uint32_t* dst) {
#pragma unroll
        for (int i = 0; i < 2; i++) {
            int q = tid + i * 256;
            int m = q >> 2, c = q & 3;
            uint4 o;
            o.x = f2tf32(ra[i].x); o.y = f2tf32(ra[i].y);
            o.z = f2tf32(ra[i].z); o.w = f2tf32(ra[i].w);
            *reinterpret_cast<uint4*>(dst + kc_off(m, c << 2)) = o;
        }
    };
    auto issueB = [&](uint32_t* dst, int k0) {
#pragma unroll
        for (int i = 0; i < 2; i++) {
            int q = tid + i * 256;
            int n = q >> 2, c = q & 3;
            cp16(dst + kc_off(n, c << 2), W + (long)(n0 + n) * IN_D + (k0 + (c << 2)));
        }
    };

    ldgA(0);
    stsA(SA);
    ldgA(BKT);
    issueB(SB, 0);            cp_commit();
    issueB(SB + SZ, BKT);     cp_commit();
    issueB(SB + 2*SZ, 2*BKT); cp_commit();

    int stage = 0;
    for (int i = 0; i < NKI; i++) {
        cp_wait2();
        __syncthreads();
        {
            int s1 = stage + 1; if (s1 >= NSTG) s1 -= NSTG;
            int s3 = stage + 3; if (s3 >= NSTG) s3 -= NSTG;
            if (i + 3 < NKI) issueB(SB + s3 * SZ, (i + 3) * BKT);
            cp_commit();
            if (i + 1 < NKI) stsA(SA + s1 * SZ);
            if (i + 2 < NKI) ldgA((i + 2) * BKT);
        }
        compute_stage<true, true>(SA + stage * SZ, SB + stage * SZ, wm0, wn0, gid, tig, acc);
        stage++; if (stage == NSTG) stage = 0;
    }

    const float* bias = g.biasm[sx];
    int cs = g.cs[sx];
    int otf = g.otf[sx];
#pragma unroll
    for (int mi = 0; mi < 4; mi++) {
        int r0 = m0 + wm0 + mi * 16 + gid;
#pragma unroll
        for (int ni = 0; ni < 4; ni++) {
            int c0 = n0 + wn0 + ni * 8 + 2 * tig;
#pragma unroll
            for (int f = 0; f < 4; f++) {
                int row = r0 + (f >> 1) * 8;
                int col = c0 + (f & 1);
                float v = acc[mi][ni][f] + bias[col];
                long idx = (long)row * cs + col;
                if (otf) ((uint32_t*)g.Cm[sx])[idx] = f2tf32(v);
                else     ((float*)g.Cm[sx])[idx]    = v;
            }
        }
    }
}

// ---------------- weight-only fp32 -> tf32 conversion ----------------
#define NW4 ((DV + 3*DK) * IN_D / 4)
__global__ void conv_w(const float4* __restrict__ wv, const float4* __restrict__ wk,
                       const float4* __restrict__ wq, const float4* __restrict__ wa)
{
    long i = (long)blockIdx.x * blockDim.x + threadIdx.x;
    if (i >= NW4) return;
    const long NWV4 = DV * IN_D / 4, NWK4 = DK * IN_D / 4;
    float4 s;
    long j = i;
    if (j < NWV4) s = wv[j];
    else { j -= NWV4;
        if (j < NWK4) s = wk[j];
        else { j -= NWK4;
            if (j < NWK4) s = wq[j];
            else s = wa[j - NWK4];
        }
    }
    uint4 o;
    o.x = f2tf32(s.x); o.y = f2tf32(s.y); o.z = f2tf32(s.z); o.w = f2tf32(s.w);
    ((uint4*)g_wt)[i] = o;
}

// ---------------- parallel decay prep (MUFU sigmoid, 256 blocks x 512 thr) ----------------
#define NSEG 8
#define SEGL (CHK / NSEG)   // 16
#define NHALF 64            // n values per block
__global__ __launch_bounds__(512) void prep_kernel() {
    int blk = blockIdx.x;                 // (c*B+b)*2 + half
    int cb = blk >> 1, half = blk & 1;
    int c = cb >> 3, b = cb & 7;
    int tid = threadIdx.x;
    int n = half * NHALF + (tid & (NHALF - 1));
    int seg = tid >> 6;                   // 8 segments x 64 n

    __shared__ float sprod[NSEG][NHALF];

    int t0 = seg * SEGL;
    float sg[SEGL];
    float p = 1.f;
#pragma unroll
    for (int i = 0; i < SEGL; i++) {
        long row = (long)(c * CHK + t0 + i) * B_DIM + b;
        float av = g_a[row * DK + n];
        float s = fmaxf(__fdividef(1.f, 1.f + __expf(-av)), EPSV);
        sg[i] = s;
        p *= s;
    }
    sprod[seg][tid & (NHALF - 1)] = p;
    __syncthreads();

    float cp = 1.f;
#pragma unroll
    for (int j = 0; j < NSEG - 1; j++)
        if (j < seg) cp *= sprod[j][tid & (NHALF - 1)];

    long base_o = ((long)cb * CHK) * DK + n;
#pragma unroll
    for (int i = 0; i < SEGL; i++) {
        int t = t0 + i;
        long row = (long)(c * CHK + t) * B_DIM + b;
        cp *= sg[i];
        g_qt[base_o + (long)t * DK] = f2tf32(g_q[row * DK + n] * cp);
        g_kt[base_o + (long)t * DK] = f2tf32(g_k[row * DK + n] / (cp + EPSV));
    }
    if (seg == NSEG - 1)
        g_cpl[(long)cb * DK + n] = cp;
}

// ---------------- inter-chunk state scan ----------------
__global__ void scan_kernel() {
    int id = blockIdx.x * blockDim.x + threadIdx.x;
    int n = id & (DK - 1);
    int d = (id >> 7) & (DV - 1);
    int b = id >> 16;
    float s = 0.f;
#pragma unroll
    for (int c = 0; c < NCH; c++) {
        long off = (((long)c * B_DIM + b) * DV + d) * DK + n;
        g_S[off] = f2tf32(s);
        float cl = g_cpl[((long)c * B_DIM + b) * DK + n];
        s = cl * (s + g_U[off]);
    }
}

// ---------------- host launcher ----------------
extern "C" void kernel_launch(void* const* d_in, const int* in_sizes, int n_in,
                              void* d_out, int out_size) {
    const float* x  = (const float*)d_in[0];
    const float* Wv = (const float*)d_in[1];
    const float* bv = (const float*)d_in[2];
    const float* Wk = (const float*)d_in[3];
    const float* bk = (const float*)d_in[4];
    const float* Wq = (const float*)d_in[5];
    const float* bq = (const float*)d_in[6];
    const float* Wa = (const float*)d_in[7];
    const float* ba = (const float*)d_in[8];
    float* y = (float*)d_out;
    (void)in_sizes; (void)n_in; (void)out_size;

    uint32_t *pwt, *pv, *pqt, *pkt, *pA, *pS;
    float *pk, *pq, *pa, *pU;
    cudaGetSymbolAddress((void**)&pwt, g_wt);
    cudaGetSymbolAddress((void**)&pv,  g_v);
    cudaGetSymbolAddress((void**)&pk,  g_k);
    cudaGetSymbolAddress((void**)&pq,  g_q);
    cudaGetSymbolAddress((void**)&pa,  g_a);
    cudaGetSymbolAddress((void**)&pqt, g_qt);
    cudaGetSymbolAddress((void**)&pkt, g_kt);
    cudaGetSymbolAddress((void**)&pA,  g_Am);
    cudaGetSymbolAddress((void**)&pU,  g_U);
    cudaGetSymbolAddress((void**)&pS,  g_S);

    static cudaStream_t s2 = 0;
    static cudaEvent_t evW = 0, evP = 0, evS = 0;
    static bool inited = false;
    if (!inited) {
        cudaStreamCreateWithFlags(&s2, cudaStreamNonBlocking);
        cudaEventCreateWithFlags(&evW, cudaEventDisableTiming);
        cudaEventCreateWithFlags(&evP, cudaEventDisableTiming);
        cudaEventCreateWithFlags(&evS, cudaEventDisableTiming);
        cudaFuncSetAttribute(proj_kernel, cudaFuncAttributeMaxDynamicSharedMemorySize, DYN_SMEM);
        cudaFuncSetAttribute(gemm_A, cudaFuncAttributeMaxDynamicSharedMemorySize, DYN_SMEM);
        cudaFuncSetAttribute(gemm_U, cudaFuncAttributeMaxDynamicSharedMemorySize, DYN_SMEM);
        cudaFuncSetAttribute(gemm_Y, cudaFuncAttributeMaxDynamicSharedMemorySize, DYN_SMEM);
        inited = true;
    }

    // ---- weight tf32 conversion ----
    conv_w<<<(NW4 + 255) / 256, 256>>>(
        (const float4*)Wv, (const float4*)Wk, (const float4*)Wq, (const float4*)Wa);

    // fork
    cudaEventRecord(evW, 0);
    cudaStreamWaitEvent(s2, evW, 0);

    ProjArgs gp;
    {
        gp.X = x;
        const long NWV4 = DV * IN_D / 4, NWK4 = DK * IN_D / 4;
        const uint32_t* wv_t = pwt;
        const uint32_t* wk_t = pwt + NWV4 * 4;
        const uint32_t* wq_t = pwt + (NWV4 + NWK4) * 4;
        const uint32_t* wa_t = pwt + (NWV4 + 2 * NWK4) * 4;
        const uint32_t* Bm[7]    = {wk_t, wq_t, wa_t, wv_t, wv_t, wv_t, wv_t};
        const float*    biasm[7] = {bk, bq, ba, bv, bv, bv, bv};
        void*           Cm[7]    = {pk, pq, pa, pv, pv, pv, pv};
        int             noff[7]  = {0, 0, 0, 0, 128, 256, 384};
        int             cs[7]    = {DK, DK, DK, DV, DV, DV, DV};
        int             otf[7]   = {0, 0, 0, 1, 1, 1, 1};
        for (int i = 0; i < 7; i++) {
            gp.Bm[i] = Bm[i]; gp.biasm[i] = biasm[i]; gp.Cm[i] = Cm[i];
            gp.noff[i] = noff[i]; gp.cs[i] = cs[i]; gp.otf[i] = otf[i];
        }
    }

    // stream0: k,q,a projections -> prep -> gemm_A -> (wait scan) fused Y
    gp.base = 0;
    proj_kernel<<<dim3(3, T_DIM * B_DIM / BM, 1), 256, DYN_SMEM, 0>>>(gp);
    // s2: v projection -> (wait prep) gemm_U -> scan
    ProjArgs gpv = gp; gpv.base = 3;
    proj_kernel<<<dim3(4, T_DIM * B_DIM / BM, 1), 256, DYN_SMEM, s2>>>(gpv);

    prep_kernel<<<NCH * B_DIM * 2, 512, 0, 0>>>();
    cudaEventRecord(evP, 0);
    gemm_A<<<NCH * B_DIM, 256, DYN_SMEM, 0>>>(pqt, pkt, pA);

    cudaStreamWaitEvent(s2, evP, 0);
    gemm_U<<<NCH * B_DIM * (DV / BM), 256, DYN_SMEM, s2>>>(pkt, pv, pU);
    scan_kernel<<<(B_DIM * DV * DK) / 256, 256, 0, s2>>>();
    cudaEventRecord(evS, s2);

    // fused Y (needs Am local; v, S via evS — s2 is serial so evS also orders v)
    cudaStreamWaitEvent(0, evS, 0);
    gemm_Y<<<dim3(DV / BN, 1, NCH * B_DIM), 256, DYN_SMEM, 0>>>(pA, pv, y, pqt, pS);
}

// round 13
// speedup vs baseline: 1.1027x; 1.0265x over previous
#include <cuda_runtime.h>
#include <math.h>
#include <stdint.h>

#define T_DIM  2048
#define B_DIM  8
#define IN_D   512
#define DV     512
#define DK     128
#define CHK    128
#define NCH    16
#define EPSV   1e-8f

#define BM  128
#define BN  128
#define BKT 16
#define NSTG 4
#define SZ   2176
#define DYN_SMEM (NSTG * SZ * 2 * 4)   // 69632 bytes
#define KCROW 16
#define KRROW 136

// proj-specific wide pipeline
#define BKT2 32
#define NST2 3
#define SZ2  4096                        // 128 rows x 32 words
#define DYN2 (NST2 * SZ2 * 2 * 4)        // 98304 bytes

// ---------------- scratch ----------------
__device__ uint32_t g_wt [(DV + 3*DK) * IN_D];
__device__ uint32_t g_v  [T_DIM*B_DIM*DV];
__device__ float    g_k  [T_DIM*B_DIM*DK];
__device__ float    g_q  [T_DIM*B_DIM*DK];
__device__ float    g_a  [T_DIM*B_DIM*DK];
__device__ uint32_t g_qt [NCH*B_DIM*CHK*DK];
__device__ uint32_t g_kt [NCH*B_DIM*CHK*DK];
__device__ float    g_cpl[NCH*B_DIM*DK];
__device__ uint32_t g_Am [NCH*B_DIM*CHK*CHK];
__device__ float    g_U  [NCH*B_DIM*DV*DK];
__device__ uint32_t g_S  [NCH*B_DIM*DV*DK];

__device__ __forceinline__ uint32_t f2tf32(float f) {
    uint32_t u;
    asm("cvt.rna.tf32.f32 %0, %1;" : "=r"(u) : "f"(f));
    return u;
}

__device__ __forceinline__ void mma_tf32(float* d, const uint32_t* a, const uint32_t* b) {
    asm volatile(
        "mma.sync.aligned.m16n8k8.row.col.f32.tf32.tf32.f32 "
        "{%0,%1,%2,%3}, {%4,%5,%6,%7}, {%8,%9}, {%0,%1,%2,%3};"
        : "+f"(d[0]), "+f"(d[1]), "+f"(d[2]), "+f"(d[3])
        : "r"(a[0]), "r"(a[1]), "r"(a[2]), "r"(a[3]),
          "r"(b[0]), "r"(b[1]));
}

__device__ __forceinline__ void cp16(uint32_t* smem, const uint32_t* g) {
    uint32_t s = (uint32_t)__cvta_generic_to_shared(smem);
    asm volatile("cp.async.cg.shared.global [%0], [%1], 16;" :: "r"(s), "l"(g));
}
__device__ __forceinline__ void cp_commit() { asm volatile("cp.async.commit_group;"); }
__device__ __forceinline__ void cp_wait2()  { asm volatile("cp.async.wait_group 2;"); }
__device__ __forceinline__ void cp_wait1()  { asm volatile("cp.async.wait_group 1;"); }

__device__ __forceinline__ int kc_off(int m, int kk) {
    return m * KCROW + (kk ^ (((m >> 1) & 3) << 2));
}
// 32-wide KC swizzle: row stride 32, kk ^ ((row&7)<<2)
__device__ __forceinline__ int kc32_off(int m, int kk) {
    return (m << 5) + (kk ^ ((m & 7) << 2));
}

// ---------------- fragment compute on one 16-K stage ----------------
template<bool AKC, bool BKC>
__device__ __forceinline__ void compute_stage(
    const uint32_t* sa, const uint32_t* sb,
    int wm0, int wn0, int gid, int tig, float acc[4][4][4])
{
#pragma unroll
    for (int ks = 0; ks < BKT; ks += 8) {
        uint32_t af[4][4], bf2[4][2];
#pragma unroll
        for (int mi = 0; mi < 4; mi++) {
            int mr = wm0 + mi * 16 + gid;
            if (AKC) {
                int fm = ((mr >> 1) & 3) << 2;
                const uint32_t* r0p = sa + mr * KCROW;
                const uint32_t* r1p = sa + (mr + 8) * KCROW;
                af[mi][0] = r0p[(ks + tig) ^ fm];
                af[mi][1] = r1p[(ks + tig) ^ fm];
                af[mi][2] = r0p[(ks + tig + 4) ^ fm];
                af[mi][3] = r1p[(ks + tig + 4) ^ fm];
            } else {
                af[mi][0] = sa[(ks + tig) * KRROW + mr];
                af[mi][1] = sa[(ks + tig) * KRROW + mr + 8];
                af[mi][2] = sa[(ks + tig + 4) * KRROW + mr];
                af[mi][3] = sa[(ks + tig + 4) * KRROW + mr + 8];
            }
        }
#pragma unroll
        for (int ni = 0; ni < 4; ni++) {
            int nc = wn0 + ni * 8 + gid;
            if (BKC) {
                int fn = ((nc >> 1) & 3) << 2;
                const uint32_t* rp = sb + nc * KCROW;
                bf2[ni][0] = rp[(ks + tig) ^ fn];
                bf2[ni][1] = rp[(ks + tig + 4) ^ fn];
            } else {
                bf2[ni][0] = sb[(ks + tig) * KRROW + nc];
                bf2[ni][1] = sb[(ks + tig + 4) * KRROW + nc];
            }
        }
#pragma unroll
        for (int mi = 0; mi < 4; mi++)
#pragma unroll
            for (int ni = 0; ni < 4; ni++)
                mma_tf32(acc[mi][ni], af[mi], bf2[ni]);
    }
}

// ---------------- 4-stage cp.async pipeline (16-K stages) ----------------
template<long ASM, long ASK, long BSK, long BSN, int KK>
__device__ __forceinline__ void pipe(
    const uint32_t* __restrict__ Ap, const uint32_t* __restrict__ Bp,
    int m0, int n0, int tid, float acc[4][4][4],
    uint32_t* SA, uint32_t* SB)
{
    constexpr bool AKC = (ASK == 1);
    constexpr bool BKC = (BSK == 1);
    constexpr int NKI = KK / BKT;
    static_assert(NKI >= 3, "pipeline needs >=3 k-iters");

    int warp = tid >> 5, lane = tid & 31;
    int wm0 = (warp & 1) * 64;
    int wn0 = (warp >> 1) * 32;
    int gid = lane >> 2, tig = lane & 3;

    auto issueA = [&](uint32_t* dst, int k0) {
#pragma unroll
        for (int i = 0; i < 2; i++) {
            int q = tid + i * 256;
            if (AKC) {
                int m = q >> 2, c = q & 3;
                cp16(dst + kc_off(m, c << 2), Ap + (long)(m0 + m) * ASM + (k0 + (c << 2)));
            } else {
                int k = q >> 5, m4 = (q & 31) << 2;
                cp16(dst + k * KRROW + m4, Ap + (long)(m0 + m4) * ASM + (long)(k0 + k) * ASK);
            }
        }
    };
    auto issueB = [&](uint32_t* dst, int k0) {
#pragma unroll
        for (int i = 0; i < 2; i++) {
            int q = tid + i * 256;
            if (BKC) {
                int n = q >> 2, c = q & 3;
                cp16(dst + kc_off(n, c << 2), Bp + (long)(n0 + n) * BSN + (k0 + (c << 2)));
            } else {
                int k = q >> 5, n4 = (q & 31) << 2;
                cp16(dst + k * KRROW + n4, Bp + (long)(k0 + k) * BSK + (long)(n0 + n4) * BSN);
            }
        }
    };

    __syncthreads();

    issueA(SA, 0);            issueB(SB, 0);            cp_commit();
    issueA(SA + SZ, BKT);     issueB(SB + SZ, BKT);     cp_commit();
    issueA(SA + 2*SZ, 2*BKT); issueB(SB + 2*SZ, 2*BKT); cp_commit();

    int stage = 0;
    for (int i = 0; i < NKI; i++) {
        cp_wait2();
        __syncthreads();
        {
            int s3 = stage + 3; if (s3 >= NSTG) s3 -= NSTG;
            if (i + 3 < NKI) {
                issueA(SA + s3 * SZ, (i + 3) * BKT);
                issueB(SB + s3 * SZ, (i + 3) * BKT);
            }
            cp_commit();
        }
        compute_stage<AKC, BKC>(SA + stage * SZ, SB + stage * SZ, wm0, wn0, gid, tig, acc);
        stage++; if (stage == NSTG) stage = 0;
    }
}

// ---------------- shared epilogue ----------------
template<long CSM, bool CAUSAL, bool OUT_TF32>
__device__ __forceinline__ void epilogue(float acc[4][4][4], void* Cbase,
                                         int m0, int n0, int tid) {
    int warp = tid >> 5, lane = tid & 31;
    int wm0 = (warp & 1) * 64, wn0 = (warp >> 1) * 32;
    int gid = lane >> 2, tig = lane & 3;
    float*    Cf = (float*)Cbase;
    uint32_t* Cu = (uint32_t*)Cbase;
#pragma unroll
    for (int mi = 0; mi < 4; mi++) {
        int r0 = m0 + wm0 + mi * 16 + gid;
#pragma unroll
        for (int ni = 0; ni < 4; ni++) {
            int c0 = n0 + wn0 + ni * 8 + 2 * tig;
#pragma unroll
            for (int f = 0; f < 4; f++) {
                int row = r0 + (f >> 1) * 8;
                int col = c0 + (f & 1);
                float v = acc[mi][ni][f];
                if (CAUSAL && col > row) v = 0.f;
                long idx = (long)row * CSM + col;
                if (OUT_TF32) Cu[idx] = f2tf32(v);
                else          Cf[idx] = v;
            }
        }
    }
}

// ---------------- A = q~ @ k~^T (causal) ----------------
__global__ __launch_bounds__(256, 2) void gemm_A(
    const uint32_t* __restrict__ qt, const uint32_t* __restrict__ kt,
    uint32_t* __restrict__ Am)
{
    extern __shared__ uint32_t dynsm[];
    uint32_t* SA = dynsm;
    uint32_t* SB = dynsm + NSTG * SZ;
    int bx = blockIdx.x, tid = threadIdx.x;

    float acc[4][4][4];
#pragma unroll
    for (int i = 0; i < 4; i++)
#pragma unroll
        for (int j = 0; j < 4; j++)
#pragma unroll
            for (int f = 0; f < 4; f++) acc[i][j][f] = 0.f;

    pipe<DK, 1, 1, DK, DK>(qt + (long)bx * CHK * DK, kt + (long)bx * CHK * DK,
                           0, 0, tid, acc, SA, SB);
    epilogue<CHK, true, true>(acc, Am + (long)bx * CHK * CHK, 0, 0, tid);
}

// ---------------- U = V^T @ k~ ----------------
__global__ __launch_bounds__(256, 2) void gemm_U(
    const uint32_t* __restrict__ kt, const uint32_t* __restrict__ v,
    float* __restrict__ U)
{
    extern __shared__ uint32_t dynsm[];
    uint32_t* SA = dynsm;
    uint32_t* SB = dynsm + NSTG * SZ;
    int q = blockIdx.x, tid = threadIdx.x;
    int mt = q & 3, zz = q >> 2;
    int cz = zz >> 3, bb = zz & 7;

    float acc[4][4][4];
#pragma unroll
    for (int i = 0; i < 4; i++)
#pragma unroll
        for (int j = 0; j < 4; j++)
#pragma unroll
            for (int f = 0; f < 4; f++) acc[i][j][f] = 0.f;

    pipe<1, (long)B_DIM * DV, DK, 1, CHK>(
        v + (long)cz * CHK * B_DIM * DV + (long)bb * DV,
        kt + (long)zz * CHK * DK, mt * BM, 0, tid, acc, SA, SB);
    epilogue<DK, false, false>(acc, U + (long)zz * DV * DK, mt * BM, 0, tid);
}

// ---------------- fused Y: y = A@V + q~@S^T ----------------
__global__ __launch_bounds__(256, 2) void gemm_Y(
    const uint32_t* __restrict__ Am, const uint32_t* __restrict__ v,
    float* __restrict__ y, const uint32_t* __restrict__ qt,
    const uint32_t* __restrict__ S)
{
    extern __shared__ uint32_t dynsm[];
    uint32_t* SA = dynsm;
    uint32_t* SB = dynsm + NSTG * SZ;

    int bz = blockIdx.z;
    int cz = bz >> 3, bb = bz & 7;
    int n0 = blockIdx.x * BN;
    int tid = threadIdx.x;

    float acc[4][4][4];
#pragma unroll
    for (int i = 0; i < 4; i++)
#pragma unroll
        for (int j = 0; j < 4; j++)
#pragma unroll
            for (int f = 0; f < 4; f++) acc[i][j][f] = 0.f;

    pipe<CHK, 1, (long)B_DIM * DV, 1, CHK>(
        Am + (long)bz * CHK * CHK,
        v + (long)cz * CHK * B_DIM * DV + (long)bb * DV,
        0, n0, tid, acc, SA, SB);
    pipe<DK, 1, 1, DK, DK>(
        qt + (long)bz * CHK * DK,
        S + (long)bz * DV * DK,
        0, n0, tid, acc, SA, SB);

    epilogue<(long)B_DIM * DV, false, false>(
        acc, y + (long)cz * CHK * B_DIM * DV + (long)bb * DV, 0, n0, tid);
}

// ---------------- projection kernel: BKT2=32, 3-stage, single barrier/iter ----------------
struct ProjArgs {
    const float* X;
    const uint32_t* Bm[7];
    const float* biasm[7];
    void* Cm[7];
    int noff[7]; int cs[7]; int otf[7];
    int base;
};

__global__ __launch_bounds__(256, 2) void proj_kernel(ProjArgs g) {
    extern __shared__ uint32_t dynsm[];
    uint32_t* SA = dynsm;                 // NST2 * SZ2
    uint32_t* SB = dynsm + NST2 * SZ2;

    int sx = blockIdx.x + g.base;
    int m0 = blockIdx.y * BM;
    int n0 = g.noff[sx];
    int tid = threadIdx.x;
    constexpr int NKI = IN_D / BKT2;      // 16

    int warp = tid >> 5, lane = tid & 31;
    int wm0 = (warp & 1) * 64, wn0 = (warp >> 1) * 32;
    int gid = lane >> 2, tig = lane & 3;

    const float* __restrict__ X = g.X;
    const uint32_t* __restrict__ W = g.Bm[sx];

    float acc[4][4][4];
#pragma unroll
    for (int i = 0; i < 4; i++)
#pragma unroll
        for (int j = 0; j < 4; j++)
#pragma unroll
            for (int f = 0; f < 4; f++) acc[i][j][f] = 0.f;

    // thread covers 4 chunks: row r = q>>3, chunk c = q&7 (16B each)
    float4 ra[4];
    auto ldgA = [&](int k0) {
#pragma unroll
        for (int i = 0; i < 4; i++) {
            int q = tid + i * 256;
            int r = q >> 3, c = q & 7;
            ra[i] = *reinterpret_cast<const float4*>(X + (long)(m0 + r) * IN_D + k0 + (c << 2));
        }
    };
    auto stsA = [&](uint32_t* dst) {
#pragma unroll
        for (int i = 0; i < 4; i++) {
            int q = tid + i * 256;
            int r = q >> 3, c = q & 7;
            uint4 o;
            o.x = f2tf32(ra[i].x); o.y = f2tf32(ra[i].y);
            o.z = f2tf32(ra[i].z); o.w = f2tf32(ra[i].w);
            *reinterpret_cast<uint4*>(dst + kc32_off(r, c << 2)) = o;
        }
    };
    auto issueB = [&](uint32_t* dst, int k0) {
#pragma unroll
        for (int i = 0; i < 4; i++) {
            int q = tid + i * 256;
            int r = q >> 3, c = q & 7;
            cp16(dst + kc32_off(r, c << 2), W + (long)(n0 + r) * IN_D + (k0 + (c << 2)));
        }
    };

    // prologue: A stage0 in smem, A stage1 in regs, B stages 0 and 1 in flight
    ldgA(0);
    stsA(SA);
    ldgA(BKT2);
    issueB(SB, 0);          cp_commit();
    issueB(SB + SZ2, BKT2); cp_commit();

    int stage = 0;
    for (int i = 0; i < NKI; i++) {
        cp_wait1();
        __syncthreads();
        {
            int s1 = stage + 1; if (s1 >= NST2) s1 -= NST2;
            int s2s = stage + 2; if (s2s >= NST2) s2s -= NST2;
            if (i + 2 < NKI) issueB(SB + s2s * SZ2, (i + 2) * BKT2);
            cp_commit();
            if (i + 1 < NKI) stsA(SA + s1 * SZ2);
            if (i + 2 < NKI) ldgA((i + 2) * BKT2);
        }
        // compute 4 k8-steps on this 32-K stage
        const uint32_t* sa = SA + stage * SZ2;
        const uint32_t* sb = SB + stage * SZ2;
#pragma unroll
        for (int ks = 0; ks < BKT2; ks += 8) {
            uint32_t af[4][4], bf2[4][2];
#pragma unroll
            for (int mi = 0; mi < 4; mi++) {
                int mr = wm0 + mi * 16 + gid;
                int fm = (mr & 7) << 2;
                const uint32_t* r0p = sa + (mr << 5);
                const uint32_t* r1p = sa + ((mr + 8) << 5);
                af[mi][0] = r0p[(ks + tig) ^ fm];
                af[mi][1] = r1p[(ks + tig) ^ fm];
                af[mi][2] = r0p[(ks + tig + 4) ^ fm];
                af[mi][3] = r1p[(ks + tig + 4) ^ fm];
            }
#pragma unroll
            for (int ni = 0; ni < 4; ni++) {
                int nc = wn0 + ni * 8 + gid;
                int fn = (nc & 7) << 2;
                const uint32_t* rp = sb + (nc << 5);
                bf2[ni][0] = rp[(ks + tig) ^ fn];
                bf2[ni][1] = rp[(ks + tig + 4) ^ fn];
            }
#pragma unroll
            for (int mi = 0; mi < 4; mi++)
#pragma unroll
                for (int ni = 0; ni < 4; ni++)
                    mma_tf32(acc[mi][ni], af[mi], bf2[ni]);
        }
        stage++; if (stage == NST2) stage = 0;
    }

    const float* bias = g.biasm[sx];
    int cs = g.cs[sx];
    int otf = g.otf[sx];
#pragma unroll
    for (int mi = 0; mi < 4; mi++) {
        int r0 = m0 + wm0 + mi * 16 + gid;
#pragma unroll
        for (int ni = 0; ni < 4; ni++) {
            int c0 = n0 + wn0 + ni * 8 + 2 * tig;
#pragma unroll
            for (int f = 0; f < 4; f++) {
                int row = r0 + (f >> 1) * 8;
                int col = c0 + (f & 1);
                float v = acc[mi][ni][f] + bias[col];
                long idx = (long)row * cs + col;
                if (otf) ((uint32_t*)g.Cm[sx])[idx] = f2tf32(v);
                else     ((float*)g.Cm[sx])[idx]    = v;
            }
        }
    }
}

// ---------------- weight-only fp32 -> tf32 conversion ----------------
#define NW4 ((DV + 3*DK) * IN_D / 4)
__global__ void conv_w(const float4* __restrict__ wv, const float4* __restrict__ wk,
                       const float4* __restrict__ wq, const float4* __restrict__ wa)
{
    long i = (long)blockIdx.x * blockDim.x + threadIdx.x;
    if (i >= NW4) return;
    const long NWV4 = DV * IN_D / 4, NWK4 = DK * IN_D / 4;
    float4 s;
    long j = i;
    if (j < NWV4) s = wv[j];
    else { j -= NWV4;
        if (j < NWK4) s = wk[j];
        else { j -= NWK4;
            if (j < NWK4) s = wq[j];
            else s = wa[j - NWK4];
        }
    }
    uint4 o;
    o.x = f2tf32(s.x); o.y = f2tf32(s.y); o.z = f2tf32(s.z); o.w = f2tf32(s.w);
    ((uint4*)g_wt)[i] = o;
}

// ---------------- parallel decay prep (MUFU sigmoid) ----------------
#define NSEG 8
#define SEGL (CHK / NSEG)   // 16
#define NHALF 64
__global__ __launch_bounds__(512) void prep_kernel() {
    int blk = blockIdx.x;
    int cb = blk >> 1, half = blk & 1;
    int c = cb >> 3, b = cb & 7;
    int tid = threadIdx.x;
    int n = half * NHALF + (tid & (NHALF - 1));
    int seg = tid >> 6;

    __shared__ float sprod[NSEG][NHALF];

    int t0 = seg * SEGL;
    float sg[SEGL];
    float p = 1.f;
#pragma unroll
    for (int i = 0; i < SEGL; i++) {
        long row = (long)(c * CHK + t0 + i) * B_DIM + b;
        float av = g_a[row * DK + n];
        float s = fmaxf(__fdividef(1.f, 1.f + __expf(-av)), EPSV);
        sg[i] = s;
        p *= s;
    }
    sprod[seg][tid & (NHALF - 1)] = p;
    __syncthreads();

    float cp = 1.f;
#pragma unroll
    for (int j = 0; j < NSEG - 1; j++)
        if (j < seg) cp *= sprod[j][tid & (NHALF - 1)];

    long base_o = ((long)cb * CHK) * DK + n;
#pragma unroll
    for (int i = 0; i < SEGL; i++) {
        int t = t0 + i;
        long row = (long)(c * CHK + t) * B_DIM + b;
        cp *= sg[i];
        g_qt[base_o + (long)t * DK] = f2tf32(g_q[row * DK + n] * cp);
        g_kt[base_o + (long)t * DK] = f2tf32(g_k[row * DK + n] / (cp + EPSV));
    }
    if (seg == NSEG - 1)
        g_cpl[(long)cb * DK + n] = cp;
}

// ---------------- inter-chunk state scan ----------------
__global__ void scan_kernel() {
    int id = blockIdx.x * blockDim.x + threadIdx.x;
    int n = id & (DK - 1);
    int d = (id >> 7) & (DV - 1);
    int b = id >> 16;
    float s = 0.f;
#pragma unroll
    for (int c = 0; c < NCH; c++) {
        long off = (((long)c * B_DIM + b) * DV + d) * DK + n;
        g_S[off] = f2tf32(s);
        float cl = g_cpl[((long)c * B_DIM + b) * DK + n];
        s = cl * (s + g_U[off]);
    }
}

// ---------------- host launcher ----------------
extern "C" void kernel_launch(void* const* d_in, const int* in_sizes, int n_in,
                              void* d_out, int out_size) {
    const float* x  = (const float*)d_in[0];
    const float* Wv = (const float*)d_in[1];
    const float* bv = (const float*)d_in[2];
    const float* Wk = (const float*)d_in[3];
    const float* bk = (const float*)d_in[4];
    const float* Wq = (const float*)d_in[5];
    const float* bq = (const float*)d_in[6];
    const float* Wa = (const float*)d_in[7];
    const float* ba = (const float*)d_in[8];
    float* y = (float*)d_out;
    (void)in_sizes; (void)n_in; (void)out_size;

    uint32_t *pwt, *pv, *pqt, *pkt, *pA, *pS;
    float *pk, *pq, *pa, *pU;
    cudaGetSymbolAddress((void**)&pwt, g_wt);
    cudaGetSymbolAddress((void**)&pv,  g_v);
    cudaGetSymbolAddress((void**)&pk,  g_k);
    cudaGetSymbolAddress((void**)&pq,  g_q);
    cudaGetSymbolAddress((void**)&pa,  g_a);
    cudaGetSymbolAddress((void**)&pqt, g_qt);
    cudaGetSymbolAddress((void**)&pkt, g_kt);
    cudaGetSymbolAddress((void**)&pA,  g_Am);
    cudaGetSymbolAddress((void**)&pU,  g_U);
    cudaGetSymbolAddress((void**)&pS,  g_S);

    static cudaStream_t s2 = 0;
    static cudaEvent_t evW = 0, evP = 0, evS = 0;
    static bool inited = false;
    if (!inited) {
        cudaStreamCreateWithFlags(&s2, cudaStreamNonBlocking);
        cudaEventCreateWithFlags(&evW, cudaEventDisableTiming);
        cudaEventCreateWithFlags(&evP, cudaEventDisableTiming);
        cudaEventCreateWithFlags(&evS, cudaEventDisableTiming);
        cudaFuncSetAttribute(proj_kernel, cudaFuncAttributeMaxDynamicSharedMemorySize, DYN2);
        cudaFuncSetAttribute(gemm_A, cudaFuncAttributeMaxDynamicSharedMemorySize, DYN_SMEM);
        cudaFuncSetAttribute(gemm_U, cudaFuncAttributeMaxDynamicSharedMemorySize, DYN_SMEM);
        cudaFuncSetAttribute(gemm_Y, cudaFuncAttributeMaxDynamicSharedMemorySize, DYN_SMEM);
        inited = true;
    }

    // ---- weight tf32 conversion ----
    conv_w<<<(NW4 + 255) / 256, 256>>>(
        (const float4*)Wv, (const float4*)Wk, (const float4*)Wq, (const float4*)Wa);

    // fork
    cudaEventRecord(evW, 0);
    cudaStreamWaitEvent(s2, evW, 0);

    ProjArgs gp;
    {
        gp.X = x;
        const long NWV4 = DV * IN_D / 4, NWK4 = DK * IN_D / 4;
        const uint32_t* wv_t = pwt;
        const uint32_t* wk_t = pwt + NWV4 * 4;
        const uint32_t* wq_t = pwt + (NWV4 + NWK4) * 4;
        const uint32_t* wa_t = pwt + (NWV4 + 2 * NWK4) * 4;
        const uint32_t* Bm[7]    = {wk_t, wq_t, wa_t, wv_t, wv_t, wv_t, wv_t};
        const float*    biasm[7] = {bk, bq, ba, bv, bv, bv, bv};
        void*           Cm[7]    = {pk, pq, pa, pv, pv, pv, pv};
        int             noff[7]  = {0, 0, 0, 0, 128, 256, 384};
        int             cs[7]    = {DK, DK, DK, DV, DV, DV, DV};
        int             otf[7]   = {0, 0, 0, 1, 1, 1, 1};
        for (int i = 0; i < 7; i++) {
            gp.Bm[i] = Bm[i]; gp.biasm[i] = biasm[i]; gp.Cm[i] = Cm[i];
            gp.noff[i] = noff[i]; gp.cs[i] = cs[i]; gp.otf[i] = otf[i];
        }
    }

    // stream0: k,q,a projections -> prep -> gemm_A -> (wait scan) fused Y
    gp.base = 0;
    proj_kernel<<<dim3(3, T_DIM * B_DIM / BM, 1), 256, DYN2, 0>>>(gp);
    // s2: v projection -> (wait prep) gemm_U -> scan
    ProjArgs gpv = gp; gpv.base = 3;
    proj_kernel<<<dim3(4, T_DIM * B_DIM / BM, 1), 256, DYN2, s2>>>(gpv);

    prep_kernel<<<NCH * B_DIM * 2, 512, 0, 0>>>();
    cudaEventRecord(evP, 0);
    gemm_A<<<NCH * B_DIM, 256, DYN_SMEM, 0>>>(pqt, pkt, pA);

    cudaStreamWaitEvent(s2, evP, 0);
    gemm_U<<<NCH * B_DIM * (DV / BM), 256, DYN_SMEM, s2>>>(pkt, pv, pU);
    scan_kernel<<<(B_DIM * DV * DK) / 256, 256, 0, s2>>>();
    cudaEventRecord(evS, s2);

    cudaStreamWaitEvent(0, evS, 0);
    gemm_Y<<<dim3(DV / BN, 1, NCH * B_DIM), 256, DYN_SMEM, 0>>>(pA, pv, y, pqt, pS);
}

// round 14
// speedup vs baseline: 1.1154x; 1.0115x over previous
#include <cuda_runtime.h>
#include <math.h>
#include <stdint.h>

#define T_DIM  2048
#define B_DIM  8
#define IN_D   512
#define DV     512
#define DK     128
#define CHK    128
#define NCH    16
#define EPSV   1e-8f

#define BM  128
#define BN  128
#define KRROW 136

// wide pipeline constants (all GEMMs)
#define BKT2 32
#define NST2 3
#define SZ2  4096                        // KC stage: 128 rows x 32 words
#define SZM  4352                        // max stage (KR: 32 x 136)
#define DYN2 (NST2 * SZ2 * 2 * 4)        // proj: 98304
#define DYNM (NST2 * SZM * 2 * 4)        // batch gemms: 104448

// ---------------- scratch ----------------
__device__ uint32_t g_wt [(DV + 3*DK) * IN_D];
__device__ uint32_t g_v  [T_DIM*B_DIM*DV];
__device__ float    g_k  [T_DIM*B_DIM*DK];
__device__ float    g_q  [T_DIM*B_DIM*DK];
__device__ float    g_a  [T_DIM*B_DIM*DK];
__device__ uint32_t g_qt [NCH*B_DIM*CHK*DK];
__device__ uint32_t g_kt [NCH*B_DIM*CHK*DK];
__device__ float    g_cpl[NCH*B_DIM*DK];
__device__ uint32_t g_Am [NCH*B_DIM*CHK*CHK];
__device__ float    g_U  [NCH*B_DIM*DV*DK];
__device__ uint32_t g_S  [NCH*B_DIM*DV*DK];

__device__ __forceinline__ uint32_t f2tf32(float f) {
    uint32_t u;
    asm("cvt.rna.tf32.f32 %0, %1;" : "=r"(u) : "f"(f));
    return u;
}

__device__ __forceinline__ void mma_tf32(float* d, const uint32_t* a, const uint32_t* b) {
    asm volatile(
        "mma.sync.aligned.m16n8k8.row.col.f32.tf32.tf32.f32 "
        "{%0,%1,%2,%3}, {%4,%5,%6,%7}, {%8,%9}, {%0,%1,%2,%3};"
        : "+f"(d[0]), "+f"(d[1]), "+f"(d[2]), "+f"(d[3])
        : "r"(a[0]), "r"(a[1]), "r"(a[2]), "r"(a[3]),
          "r"(b[0]), "r"(b[1]));
}

__device__ __forceinline__ void cp16(uint32_t* smem, const uint32_t* g) {
    uint32_t s = (uint32_t)__cvta_generic_to_shared(smem);
    asm volatile("cp.async.cg.shared.global [%0], [%1], 16;" :: "r"(s), "l"(g));
}
__device__ __forceinline__ void cp_commit() { asm volatile("cp.async.commit_group;"); }
__device__ __forceinline__ void cp_wait1()  { asm volatile("cp.async.wait_group 1;"); }

// 32-wide KC swizzle: row stride 32, kk ^ ((row&7)<<2)
__device__ __forceinline__ int kc32_off(int m, int kk) {
    return (m << 5) + (kk ^ ((m & 7) << 2));
}

// ---------------- 32-K-stage, 3-stage, 1-barrier pipeline (both ops cp.async) ----------------
template<long ASM, long ASK, long BSK, long BSN, int KK>
__device__ __forceinline__ void pipe32(
    const uint32_t* __restrict__ Ap, const uint32_t* __restrict__ Bp,
    int m0, int n0, int tid, float acc[4][4][4],
    uint32_t* SA, uint32_t* SB)
{
    constexpr bool AKC = (ASK == 1);
    constexpr bool BKC = (BSK == 1);
    constexpr int NKI = KK / BKT2;
    static_assert(NKI >= 2, "pipe32 needs >=2 k-iters");

    int warp = tid >> 5, lane = tid & 31;
    int wm0 = (warp & 1) * 64;
    int wn0 = (warp >> 1) * 32;
    int gid = lane >> 2, tig = lane & 3;

    auto issueA = [&](uint32_t* dst, int k0) {
#pragma unroll
        for (int i = 0; i < 4; i++) {
            int q = tid + i * 256;
            if (AKC) {
                int r = q >> 3, c = q & 7;
                cp16(dst + kc32_off(r, c << 2), Ap + (long)(m0 + r) * ASM + (k0 + (c << 2)));
            } else {
                int k = q >> 5, r4 = (q & 31) << 2;
                cp16(dst + k * KRROW + r4, Ap + (long)(m0 + r4) * ASM + (long)(k0 + k) * ASK);
            }
        }
    };
    auto issueB = [&](uint32_t* dst, int k0) {
#pragma unroll
        for (int i = 0; i < 4; i++) {
            int q = tid + i * 256;
            if (BKC) {
                int r = q >> 3, c = q & 7;
                cp16(dst + kc32_off(r, c << 2), Bp + (long)(n0 + r) * BSN + (k0 + (c << 2)));
            } else {
                int k = q >> 5, r4 = (q & 31) << 2;
                cp16(dst + k * KRROW + r4, Bp + (long)(k0 + k) * BSK + (long)(n0 + r4) * BSN);
            }
        }
    };

    __syncthreads();   // protect buffers from previous use

    issueA(SA, 0);           issueB(SB, 0);           cp_commit();
    issueA(SA + SZM, BKT2);  issueB(SB + SZM, BKT2);  cp_commit();

    int stage = 0;
    for (int i = 0; i < NKI; i++) {
        cp_wait1();
        __syncthreads();
        {
            int s2s = stage + 2; if (s2s >= NST2) s2s -= NST2;
            if (i + 2 < NKI) {
                issueA(SA + s2s * SZM, (i + 2) * BKT2);
                issueB(SB + s2s * SZM, (i + 2) * BKT2);
            }
            cp_commit();
        }
        const uint32_t* sa = SA + stage * SZM;
        const uint32_t* sb = SB + stage * SZM;
#pragma unroll
        for (int ks = 0; ks < BKT2; ks += 8) {
            uint32_t af[4][4], bf2[4][2];
#pragma unroll
            for (int mi = 0; mi < 4; mi++) {
                int mr = wm0 + mi * 16 + gid;
                if (AKC) {
                    int fm = (mr & 7) << 2;
                    const uint32_t* r0p = sa + (mr << 5);
                    const uint32_t* r1p = sa + ((mr + 8) << 5);
                    af[mi][0] = r0p[(ks + tig) ^ fm];
                    af[mi][1] = r1p[(ks + tig) ^ fm];
                    af[mi][2] = r0p[(ks + tig + 4) ^ fm];
                    af[mi][3] = r1p[(ks + tig + 4) ^ fm];
                } else {
                    af[mi][0] = sa[(ks + tig) * KRROW + mr];
                    af[mi][1] = sa[(ks + tig) * KRROW + mr + 8];
                    af[mi][2] = sa[(ks + tig + 4) * KRROW + mr];
                    af[mi][3] = sa[(ks + tig + 4) * KRROW + mr + 8];
                }
            }
#pragma unroll
            for (int ni = 0; ni < 4; ni++) {
                int nc = wn0 + ni * 8 + gid;
                if (BKC) {
                    int fn = (nc & 7) << 2;
                    const uint32_t* rp = sb + (nc << 5);
                    bf2[ni][0] = rp[(ks + tig) ^ fn];
                    bf2[ni][1] = rp[(ks + tig + 4) ^ fn];
                } else {
                    bf2[ni][0] = sb[(ks + tig) * KRROW + nc];
                    bf2[ni][1] = sb[(ks + tig + 4) * KRROW + nc];
                }
            }
#pragma unroll
            for (int mi = 0; mi < 4; mi++)
#pragma unroll
                for (int ni = 0; ni < 4; ni++)
                    mma_tf32(acc[mi][ni], af[mi], bf2[ni]);
        }
        stage++; if (stage == NST2) stage = 0;
    }
}

// ---------------- shared epilogue ----------------
template<long CSM, bool CAUSAL, bool OUT_TF32>
__device__ __forceinline__ void epilogue(float acc[4][4][4], void* Cbase,
                                         int m0, int n0, int tid) {
    int warp = tid >> 5, lane = tid & 31;
    int wm0 = (warp & 1) * 64, wn0 = (warp >> 1) * 32;
    int gid = lane >> 2, tig = lane & 3;
    float*    Cf = (float*)Cbase;
    uint32_t* Cu = (uint32_t*)Cbase;
#pragma unroll
    for (int mi = 0; mi < 4; mi++) {
        int r0 = m0 + wm0 + mi * 16 + gid;
#pragma unroll
        for (int ni = 0; ni < 4; ni++) {
            int c0 = n0 + wn0 + ni * 8 + 2 * tig;
#pragma unroll
            for (int f = 0; f < 4; f++) {
                int row = r0 + (f >> 1) * 8;
                int col = c0 + (f & 1);
                float v = acc[mi][ni][f];
                if (CAUSAL && col > row) v = 0.f;
                long idx = (long)row * CSM + col;
                if (OUT_TF32) Cu[idx] = f2tf32(v);
                else          Cf[idx] = v;
            }
        }
    }
}

#define ZERO_ACC(acc) \
    _Pragma("unroll") for (int i = 0; i < 4; i++) \
    _Pragma("unroll") for (int j = 0; j < 4; j++) \
    _Pragma("unroll") for (int f = 0; f < 4; f++) acc[i][j][f] = 0.f;

// ---------------- A = q~ @ k~^T (causal) ----------------
__global__ __launch_bounds__(256, 2) void gemm_A(
    const uint32_t* __restrict__ qt, const uint32_t* __restrict__ kt,
    uint32_t* __restrict__ Am)
{
    extern __shared__ uint32_t dynsm[];
    uint32_t* SA = dynsm;
    uint32_t* SB = dynsm + NST2 * SZM;
    int bx = blockIdx.x, tid = threadIdx.x;

    float acc[4][4][4];
    ZERO_ACC(acc)

    pipe32<DK, 1, 1, DK, DK>(qt + (long)bx * CHK * DK, kt + (long)bx * CHK * DK,
                             0, 0, tid, acc, SA, SB);
    epilogue<CHK, true, true>(acc, Am + (long)bx * CHK * CHK, 0, 0, tid);
}

// ---------------- U = V^T @ k~ ----------------
__global__ __launch_bounds__(256, 2) void gemm_U(
    const uint32_t* __restrict__ kt, const uint32_t* __restrict__ v,
    float* __restrict__ U)
{
    extern __shared__ uint32_t dynsm[];
    uint32_t* SA = dynsm;
    uint32_t* SB = dynsm + NST2 * SZM;
    int q = blockIdx.x, tid = threadIdx.x;
    int mt = q & 3, zz = q >> 2;
    int cz = zz >> 3, bb = zz & 7;

    float acc[4][4][4];
    ZERO_ACC(acc)

    pipe32<1, (long)B_DIM * DV, DK, 1, CHK>(
        v + (long)cz * CHK * B_DIM * DV + (long)bb * DV,
        kt + (long)zz * CHK * DK, mt * BM, 0, tid, acc, SA, SB);
    epilogue<DK, false, false>(acc, U + (long)zz * DV * DK, mt * BM, 0, tid);
}

// ---------------- fused Y: y = A@V + q~@S^T ----------------
__global__ __launch_bounds__(256, 2) void gemm_Y(
    const uint32_t* __restrict__ Am, const uint32_t* __restrict__ v,
    float* __restrict__ y, const uint32_t* __restrict__ qt,
    const uint32_t* __restrict__ S)
{
    extern __shared__ uint32_t dynsm[];
    uint32_t* SA = dynsm;
    uint32_t* SB = dynsm + NST2 * SZM;

    int bz = blockIdx.z;
    int cz = bz >> 3, bb = bz & 7;
    int n0 = blockIdx.x * BN;
    int tid = threadIdx.x;

    float acc[4][4][4];
    ZERO_ACC(acc)

    pipe32<CHK, 1, (long)B_DIM * DV, 1, CHK>(
        Am + (long)bz * CHK * CHK,
        v + (long)cz * CHK * B_DIM * DV + (long)bb * DV,
        0, n0, tid, acc, SA, SB);
    pipe32<DK, 1, 1, DK, DK>(
        qt + (long)bz * CHK * DK,
        S + (long)bz * DV * DK,
        0, n0, tid, acc, SA, SB);

    epilogue<(long)B_DIM * DV, false, false>(
        acc, y + (long)cz * CHK * B_DIM * DV + (long)bb * DV, 0, n0, tid);
}

// ---------------- projection kernel: BKT2=32, 3-stage, single barrier/iter ----------------
struct ProjArgs {
    const float* X;
    const uint32_t* Bm[7];
    const float* biasm[7];
    void* Cm[7];
    int noff[7]; int cs[7]; int otf[7];
    int base;
};

__global__ __launch_bounds__(256, 2) void proj_kernel(ProjArgs g) {
    extern __shared__ uint32_t dynsm[];
    uint32_t* SA = dynsm;                 // NST2 * SZ2
    uint32_t* SB = dynsm + NST2 * SZ2;

    int sx = blockIdx.x + g.base;
    int m0 = blockIdx.y * BM;
    int n0 = g.noff[sx];
    int tid = threadIdx.x;
    constexpr int NKI = IN_D / BKT2;      // 16

    int warp = tid >> 5, lane = tid & 31;
    int wm0 = (warp & 1) * 64, wn0 = (warp >> 1) * 32;
    int gid = lane >> 2, tig = lane & 3;

    const float* __restrict__ X = g.X;
    const uint32_t* __restrict__ W = g.Bm[sx];

    float acc[4][4][4];
    ZERO_ACC(acc)

    float4 ra[4];
    auto ldgA = [&](int k0) {
#pragma unroll
        for (int i = 0; i < 4; i++) {
            int q = tid + i * 256;
            int r = q >> 3, c = q & 7;
            ra[i] = *reinterpret_cast<const float4*>(X + (long)(m0 + r) * IN_D + k0 + (c << 2));
        }
    };
    auto stsA = [&](uint32_t* dst) {
#pragma unroll
        for (int i = 0; i < 4; i++) {
            int q = tid + i * 256;
            int r = q >> 3, c = q & 7;
            uint4 o;
            o.x = f2tf32(ra[i].x); o.y = f2tf32(ra[i].y);
            o.z = f2tf32(ra[i].z); o.w = f2tf32(ra[i].w);
            *reinterpret_cast<uint4*>(dst + kc32_off(r, c << 2)) = o;
        }
    };
    auto issueB = [&](uint32_t* dst, int k0) {
#pragma unroll
        for (int i = 0; i < 4; i++) {
            int q = tid + i * 256;
            int r = q >> 3, c = q & 7;
            cp16(dst + kc32_off(r, c << 2), W + (long)(n0 + r) * IN_D + (k0 + (c << 2)));
        }
    };

    ldgA(0);
    stsA(SA);
    ldgA(BKT2);
    issueB(SB, 0);          cp_commit();
    issueB(SB + SZ2, BKT2); cp_commit();

    int stage = 0;
    for (int i = 0; i < NKI; i++) {
        cp_wait1();
        __syncthreads();
        {
            int s1 = stage + 1; if (s1 >= NST2) s1 -= NST2;
            int s2s = stage + 2; if (s2s >= NST2) s2s -= NST2;
            if (i + 2 < NKI) issueB(SB + s2s * SZ2, (i + 2) * BKT2);
            cp_commit();
            if (i + 1 < NKI) stsA(SA + s1 * SZ2);
            if (i + 2 < NKI) ldgA((i + 2) * BKT2);
        }
        const uint32_t* sa = SA + stage * SZ2;
        const uint32_t* sb = SB + stage * SZ2;
#pragma unroll
        for (int ks = 0; ks < BKT2; ks += 8) {
            uint32_t af[4][4], bf2[4][2];
#pragma unroll
            for (int mi = 0; mi < 4; mi++) {
                int mr = wm0 + mi * 16 + gid;
                int fm = (mr & 7) << 2;
                const uint32_t* r0p = sa + (mr << 5);
                const uint32_t* r1p = sa + ((mr + 8) << 5);
                af[mi][0] = r0p[(ks + tig) ^ fm];
                af[mi][1] = r1p[(ks + tig) ^ fm];
                af[mi][2] = r0p[(ks + tig + 4) ^ fm];
                af[mi][3] = r1p[(ks + tig + 4) ^ fm];
            }
#pragma unroll
            for (int ni = 0; ni < 4; ni++) {
                int nc = wn0 + ni * 8 + gid;
                int fn = (nc & 7) << 2;
                const uint32_t* rp = sb + (nc << 5);
                bf2[ni][0] = rp[(ks + tig) ^ fn];
                bf2[ni][1] = rp[(ks + tig + 4) ^ fn];
            }
#pragma unroll
            for (int mi = 0; mi < 4; mi++)
#pragma unroll
                for (int ni = 0; ni < 4; ni++)
                    mma_tf32(acc[mi][ni], af[mi], bf2[ni]);
        }
        stage++; if (stage == NST2) stage = 0;
    }

    const float* bias = g.biasm[sx];
    int cs = g.cs[sx];
    int otf = g.otf[sx];
#pragma unroll
    for (int mi = 0; mi < 4; mi++) {
        int r0 = m0 + wm0 + mi * 16 + gid;
#pragma unroll
        for (int ni = 0; ni < 4; ni++) {
            int c0 = n0 + wn0 + ni * 8 + 2 * tig;
#pragma unroll
            for (int f = 0; f < 4; f++) {
                int row = r0 + (f >> 1) * 8;
                int col = c0 + (f & 1);
                float v = acc[mi][ni][f] + bias[col];
                long idx = (long)row * cs + col;
                if (otf) ((uint32_t*)g.Cm[sx])[idx] = f2tf32(v);
                else     ((float*)g.Cm[sx])[idx]    = v;
            }
        }
    }
}

// ---------------- weight-only fp32 -> tf32 conversion ----------------
#define NW4 ((DV + 3*DK) * IN_D / 4)
__global__ void conv_w(const float4* __restrict__ wv, const float4* __restrict__ wk,
                       const float4* __restrict__ wq, const float4* __restrict__ wa)
{
    long i = (long)blockIdx.x * blockDim.x + threadIdx.x;
    if (i >= NW4) return;
    const long NWV4 = DV * IN_D / 4, NWK4 = DK * IN_D / 4;
    float4 s;
    long j = i;
    if (j < NWV4) s = wv[j];
    else { j -= NWV4;
        if (j < NWK4) s = wk[j];
        else { j -= NWK4;
            if (j < NWK4) s = wq[j];
            else s = wa[j - NWK4];
        }
    }
    uint4 o;
    o.x = f2tf32(s.x); o.y = f2tf32(s.y); o.z = f2tf32(s.z); o.w = f2tf32(s.w);
    ((uint4*)g_wt)[i] = o;
}

// ---------------- parallel decay prep (MUFU sigmoid) ----------------
#define NSEG 8
#define SEGL (CHK / NSEG)   // 16
#define NHALF 64
__global__ __launch_bounds__(512) void prep_kernel() {
    int blk = blockIdx.x;
    int cb = blk >> 1, half = blk & 1;
    int c = cb >> 3, b = cb & 7;
    int tid = threadIdx.x;
    int n = half * NHALF + (tid & (NHALF - 1));
    int seg = tid >> 6;

    __shared__ float sprod[NSEG][NHALF];

    int t0 = seg * SEGL;
    float sg[SEGL];
    float p = 1.f;
#pragma unroll
    for (int i = 0; i < SEGL; i++) {
        long row = (long)(c * CHK + t0 + i) * B_DIM + b;
        float av = g_a[row * DK + n];
        float s = fmaxf(__fdividef(1.f, 1.f + __expf(-av)), EPSV);
        sg[i] = s;
        p *= s;
    }
    sprod[seg][tid & (NHALF - 1)] = p;
    __syncthreads();

    float cp = 1.f;
#pragma unroll
    for (int j = 0; j < NSEG - 1; j++)
        if (j < seg) cp *= sprod[j][tid & (NHALF - 1)];

    long base_o = ((long)cb * CHK) * DK + n;
#pragma unroll
    for (int i = 0; i < SEGL; i++) {
        int t = t0 + i;
        long row = (long)(c * CHK + t) * B_DIM + b;
        cp *= sg[i];
        g_qt[base_o + (long)t * DK] = f2tf32(g_q[row * DK + n] * cp);
        g_kt[base_o + (long)t * DK] = f2tf32(g_k[row * DK + n] / (cp + EPSV));
    }
    if (seg == NSEG - 1)
        g_cpl[(long)cb * DK + n] = cp;
}

// ---------------- inter-chunk state scan ----------------
__global__ void scan_kernel() {
    int id = blockIdx.x * blockDim.x + threadIdx.x;
    int n = id & (DK - 1);
    int d = (id >> 7) & (DV - 1);
    int b = id >> 16;
    float s = 0.f;
#pragma unroll
    for (int c = 0; c < NCH; c++) {
        long off = (((long)c * B_DIM + b) * DV + d) * DK + n;
        g_S[off] = f2tf32(s);
        float cl = g_cpl[((long)c * B_DIM + b) * DK + n];
        s = cl * (s + g_U[off]);
    }
}

// ---------------- host launcher ----------------
extern "C" void kernel_launch(void* const* d_in, const int* in_sizes, int n_in,
                              void* d_out, int out_size) {
    const float* x  = (const float*)d_in[0];
    const float* Wv = (const float*)d_in[1];
    const float* bv = (const float*)d_in[2];
    const float* Wk = (const float*)d_in[3];
    const float* bk = (const float*)d_in[4];
    const float* Wq = (const float*)d_in[5];
    const float* bq = (const float*)d_in[6];
    const float* Wa = (const float*)d_in[7];
    const float* ba = (const float*)d_in[8];
    float* y = (float*)d_out;
    (void)in_sizes; (void)n_in; (void)out_size;

    uint32_t *pwt, *pv, *pqt, *pkt, *pA, *pS;
    float *pk, *pq, *pa, *pU;
    cudaGetSymbolAddress((void**)&pwt, g_wt);
    cudaGetSymbolAddress((void**)&pv,  g_v);
    cudaGetSymbolAddress((void**)&pk,  g_k);
    cudaGetSymbolAddress((void**)&pq,  g_q);
    cudaGetSymbolAddress((void**)&pa,  g_a);
    cudaGetSymbolAddress((void**)&pqt, g_qt);
    cudaGetSymbolAddress((void**)&pkt, g_kt);
    cudaGetSymbolAddress((void**)&pA,  g_Am);
    cudaGetSymbolAddress((void**)&pU,  g_U);
    cudaGetSymbolAddress((void**)&pS,  g_S);

    static cudaStream_t s2 = 0;
    static cudaEvent_t evW = 0, evP = 0, evS = 0;
    static bool inited = false;
    if (!inited) {
        cudaStreamCreateWithFlags(&s2, cudaStreamNonBlocking);
        cudaEventCreateWithFlags(&evW, cudaEventDisableTiming);
        cudaEventCreateWithFlags(&evP, cudaEventDisableTiming);
        cudaEventCreateWithFlags(&evS, cudaEventDisableTiming);
        cudaFuncSetAttribute(proj_kernel, cudaFuncAttributeMaxDynamicSharedMemorySize, DYN2);
        cudaFuncSetAttribute(gemm_A, cudaFuncAttributeMaxDynamicSharedMemorySize, DYNM);
        cudaFuncSetAttribute(gemm_U, cudaFuncAttributeMaxDynamicSharedMemorySize, DYNM);
        cudaFuncSetAttribute(gemm_Y, cudaFuncAttributeMaxDynamicSharedMemorySize, DYNM);
        inited = true;
    }

    // ---- weight tf32 conversion ----
    conv_w<<<(NW4 + 255) / 256, 256>>>(
        (const float4*)Wv, (const float4*)Wk, (const float4*)Wq, (const float4*)Wa);

    // fork
    cudaEventRecord(evW, 0);
    cudaStreamWaitEvent(s2, evW, 0);

    ProjArgs gp;
    {
        gp.X = x;
        const long NWV4 = DV * IN_D / 4, NWK4 = DK * IN_D / 4;
        const uint32_t* wv_t = pwt;
        const uint32_t* wk_t = pwt + NWV4 * 4;
        const uint32_t* wq_t = pwt + (NWV4 + NWK4) * 4;
        const uint32_t* wa_t = pwt + (NWV4 + 2 * NWK4) * 4;
        const uint32_t* Bm[7]    = {wk_t, wq_t, wa_t, wv_t, wv_t, wv_t, wv_t};
        const float*    biasm[7] = {bk, bq, ba, bv, bv, bv, bv};
        void*           Cm[7]    = {pk, pq, pa, pv, pv, pv, pv};
        int             noff[7]  = {0, 0, 0, 0, 128, 256, 384};
        int             cs[7]    = {DK, DK, DK, DV, DV, DV, DV};
        int             otf[7]   = {0, 0, 0, 1, 1, 1, 1};
        for (int i = 0; i < 7; i++) {
            gp.Bm[i] = Bm[i]; gp.biasm[i] = biasm[i]; gp.Cm[i] = Cm[i];
            gp.noff[i] = noff[i]; gp.cs[i] = cs[i]; gp.otf[i] = otf[i];
        }
    }

    // stream0: k,q,a projections -> prep -> gemm_A -> (wait scan) fused Y
    gp.base = 0;
    proj_kernel<<<dim3(3, T_DIM * B_DIM / BM, 1), 256, DYN2, 0>>>(gp);
    // s2: v projection -> (wait prep) gemm_U -> scan
    ProjArgs gpv = gp; gpv.base = 3;
    proj_kernel<<<dim3(4, T_DIM * B_DIM / BM, 1), 256, DYN2, s2>>>(gpv);

    prep_kernel<<<NCH * B_DIM * 2, 512, 0, 0>>>();
    cudaEventRecord(evP, 0);
    gemm_A<<<NCH * B_DIM, 256, DYNM, 0>>>(pqt, pkt, pA);

    cudaStreamWaitEvent(s2, evP, 0);
    gemm_U<<<NCH * B_DIM * (DV / BM), 256, DYNM, s2>>>(pkt, pv, pU);
    scan_kernel<<<(B_DIM * DV * DK) / 256, 256, 0, s2>>>();
    cudaEventRecord(evS, s2);

    cudaStreamWaitEvent(0, evS, 0);
    gemm_Y<<<dim3(DV / BN, 1, NCH * B_DIM), 256, DYNM, 0>>>(pA, pv, y, pqt, pS);
}

// round 15
// speedup vs baseline: 1.1367x; 1.0191x over previous
#include <cuda_runtime.h>
#include <math.h>
#include <stdint.h>

#define T_DIM  2048
#define B_DIM  8
#define IN_D   512
#define DV     512
#define DK     128
#define CHK    128
#define NCH    16
#define EPSV   1e-8f

#define BM  128
#define BN  128
#define KRROW 136

#define BKT2 32
#define NST2 3
#define SZ2  4096
#define SZM  4352
#define DYN2 (NST2 * SZ2 * 2 * 4)        // proj: 98304
#define DYNM (NST2 * SZM * 2 * 4)        // batch gemms: 104448

// paired position within each 8-group of the contraction axis
__host__ __device__ __forceinline__ int PPAIR(int k) {
    return (k & ~7) | ((k & 3) << 1) | ((k >> 2) & 1);
}

// ---------------- scratch ----------------
__device__ uint32_t g_wt [(DV + 3*DK) * IN_D];   // weights, k PAIRED
__device__ uint32_t g_v  [T_DIM*B_DIM*DV];
__device__ float    g_k  [T_DIM*B_DIM*DK];
__device__ float    g_q  [T_DIM*B_DIM*DK];
__device__ float    g_a  [T_DIM*B_DIM*DK];
__device__ uint32_t g_qt [NCH*B_DIM*CHK*DK];     // n PAIRED
__device__ uint32_t g_kt [NCH*B_DIM*CHK*DK];     // n PAIRED
__device__ float    g_cpl[NCH*B_DIM*DK];         // n PAIRED
__device__ uint32_t g_Am [NCH*B_DIM*CHK*CHK];    // plain
__device__ float    g_U  [NCH*B_DIM*DV*DK];      // n PAIRED (inherited)
__device__ uint32_t g_S  [NCH*B_DIM*DV*DK];      // n PAIRED (inherited)

__device__ __forceinline__ uint32_t f2tf32(float f) {
    uint32_t u;
    asm("cvt.rna.tf32.f32 %0, %1;" : "=r"(u) : "f"(f));
    return u;
}

__device__ __forceinline__ void mma_tf32(float* d, const uint32_t* a, const uint32_t* b) {
    asm volatile(
        "mma.sync.aligned.m16n8k8.row.col.f32.tf32.tf32.f32 "
        "{%0,%1,%2,%3}, {%4,%5,%6,%7}, {%8,%9}, {%0,%1,%2,%3};"
        : "+f"(d[0]), "+f"(d[1]), "+f"(d[2]), "+f"(d[3])
        : "r"(a[0]), "r"(a[1]), "r"(a[2]), "r"(a[3]),
          "r"(b[0]), "r"(b[1]));
}

__device__ __forceinline__ void cp16(uint32_t* smem, const uint32_t* g) {
    uint32_t s = (uint32_t)__cvta_generic_to_shared(smem);
    asm volatile("cp.async.cg.shared.global [%0], [%1], 16;" :: "r"(s), "l"(g));
}
__device__ __forceinline__ void cp_commit() { asm volatile("cp.async.commit_group;"); }
__device__ __forceinline__ void cp_wait1()  { asm volatile("cp.async.wait_group 1;"); }

// plain 32-wide KC swizzle
__device__ __forceinline__ int kc32_off(int m, int kk) {
    return (m << 5) + (kk ^ ((m & 7) << 2));
}
// paired 32-wide KC swizzle (8-word granule XOR keeps 16B blocks)
__device__ __forceinline__ int kp32_off(int m, int kk) {
    return (m << 5) + (kk ^ ((m & 3) << 3));
}

// ---------------- 32-K-stage pipeline; AP/BP = paired-KC flags ----------------
template<long ASM, long ASK, long BSK, long BSN, int KK, bool AP, bool BP>
__device__ __forceinline__ void pipe32(
    const uint32_t* __restrict__ Ap, const uint32_t* __restrict__ Bp,
    int m0, int n0, int tid, float acc[4][4][4],
    uint32_t* SA, uint32_t* SB)
{
    constexpr bool AKC = (ASK == 1);
    constexpr bool BKC = (BSK == 1);
    constexpr int NKI = KK / BKT2;
    static_assert(NKI >= 2, "pipe32 needs >=2 k-iters");

    int warp = tid >> 5, lane = tid & 31;
    int wm0 = (warp & 1) * 64;
    int wn0 = (warp >> 1) * 32;
    int gid = lane >> 2, tig = lane & 3;

    auto issueA = [&](uint32_t* dst, int k0) {
#pragma unroll
        for (int i = 0; i < 4; i++) {
            int q = tid + i * 256;
            if (AKC) {
                int r = q >> 3, c = q & 7;
                int off = AP ? kp32_off(r, c << 2) : kc32_off(r, c << 2);
                cp16(dst + off, Ap + (long)(m0 + r) * ASM + (k0 + (c << 2)));
            } else {
                int k = q >> 5, r4 = (q & 31) << 2;
                cp16(dst + k * KRROW + r4, Ap + (long)(m0 + r4) * ASM + (long)(k0 + k) * ASK);
            }
        }
    };
    auto issueB = [&](uint32_t* dst, int k0) {
#pragma unroll
        for (int i = 0; i < 4; i++) {
            int q = tid + i * 256;
            if (BKC) {
                int r = q >> 3, c = q & 7;
                int off = BP ? kp32_off(r, c << 2) : kc32_off(r, c << 2);
                cp16(dst + off, Bp + (long)(n0 + r) * BSN + (k0 + (c << 2)));
            } else {
                int k = q >> 5, r4 = (q & 31) << 2;
                cp16(dst + k * KRROW + r4, Bp + (long)(k0 + k) * BSK + (long)(n0 + r4) * BSN);
            }
        }
    };

    __syncthreads();

    issueA(SA, 0);           issueB(SB, 0);           cp_commit();
    issueA(SA + SZM, BKT2);  issueB(SB + SZM, BKT2);  cp_commit();

    int stage = 0;
    for (int i = 0; i < NKI; i++) {
        cp_wait1();
        __syncthreads();
        {
            int s2s = stage + 2; if (s2s >= NST2) s2s -= NST2;
            if (i + 2 < NKI) {
                issueA(SA + s2s * SZM, (i + 2) * BKT2);
                issueB(SB + s2s * SZM, (i + 2) * BKT2);
            }
            cp_commit();
        }
        const uint32_t* sa = SA + stage * SZM;
        const uint32_t* sb = SB + stage * SZM;
#pragma unroll
        for (int ks = 0; ks < BKT2; ks += 8) {
            uint32_t af[4][4], bf2[4][2];
#pragma unroll
            for (int mi = 0; mi < 4; mi++) {
                int mr = wm0 + mi * 16 + gid;
                if (AKC) {
                    if (AP) {
                        int base = (ks + tig * 2);
                        uint2 lo = *reinterpret_cast<const uint2*>(
                            sa + (mr << 5) + (base ^ ((mr & 3) << 3)));
                        uint2 hi = *reinterpret_cast<const uint2*>(
                            sa + ((mr + 8) << 5) + (base ^ (((mr + 8) & 3) << 3)));
                        af[mi][0] = lo.x; af[mi][2] = lo.y;
                        af[mi][1] = hi.x; af[mi][3] = hi.y;
                    } else {
                        int fm = (mr & 7) << 2;
                        const uint32_t* r0p = sa + (mr << 5);
                        const uint32_t* r1p = sa + ((mr + 8) << 5);
                        af[mi][0] = r0p[(ks + tig) ^ fm];
                        af[mi][1] = r1p[(ks + tig) ^ fm];
                        af[mi][2] = r0p[(ks + tig + 4) ^ fm];
                        af[mi][3] = r1p[(ks + tig + 4) ^ fm];
                    }
                } else {
                    af[mi][0] = sa[(ks + tig) * KRROW + mr];
                    af[mi][1] = sa[(ks + tig) * KRROW + mr + 8];
                    af[mi][2] = sa[(ks + tig + 4) * KRROW + mr];
                    af[mi][3] = sa[(ks + tig + 4) * KRROW + mr + 8];
                }
            }
#pragma unroll
            for (int ni = 0; ni < 4; ni++) {
                int nc = wn0 + ni * 8 + gid;
                if (BKC) {
                    if (BP) {
                        uint2 p = *reinterpret_cast<const uint2*>(
                            sb + (nc << 5) + ((ks + tig * 2) ^ ((nc & 3) << 3)));
                        bf2[ni][0] = p.x; bf2[ni][1] = p.y;
                    } else {
                        int fn = (nc & 7) << 2;
                        const uint32_t* rp = sb + (nc << 5);
                        bf2[ni][0] = rp[(ks + tig) ^ fn];
                        bf2[ni][1] = rp[(ks + tig + 4) ^ fn];
                    }
                } else {
                    bf2[ni][0] = sb[(ks + tig) * KRROW + nc];
                    bf2[ni][1] = sb[(ks + tig + 4) * KRROW + nc];
                }
            }
#pragma unroll
            for (int mi = 0; mi < 4; mi++)
#pragma unroll
                for (int ni = 0; ni < 4; ni++)
                    mma_tf32(acc[mi][ni], af[mi], bf2[ni]);
        }
        stage++; if (stage == NST2) stage = 0;
    }
}

// ---------------- shared epilogue ----------------
template<long CSM, bool CAUSAL, bool OUT_TF32>
__device__ __forceinline__ void epilogue(float acc[4][4][4], void* Cbase,
                                         int m0, int n0, int tid) {
    int warp = tid >> 5, lane = tid & 31;
    int wm0 = (warp & 1) * 64, wn0 = (warp >> 1) * 32;
    int gid = lane >> 2, tig = lane & 3;
    float*    Cf = (float*)Cbase;
    uint32_t* Cu = (uint32_t*)Cbase;
#pragma unroll
    for (int mi = 0; mi < 4; mi++) {
        int r0 = m0 + wm0 + mi * 16 + gid;
#pragma unroll
        for (int ni = 0; ni < 4; ni++) {
            int c0 = n0 + wn0 + ni * 8 + 2 * tig;
#pragma unroll
            for (int f = 0; f < 4; f++) {
                int row = r0 + (f >> 1) * 8;
                int col = c0 + (f & 1);
                float v = acc[mi][ni][f];
                if (CAUSAL && col > row) v = 0.f;
                long idx = (long)row * CSM + col;
                if (OUT_TF32) Cu[idx] = f2tf32(v);
                else          Cf[idx] = v;
            }
        }
    }
}

#define ZERO_ACC(acc) \
    _Pragma("unroll") for (int i = 0; i < 4; i++) \
    _Pragma("unroll") for (int j = 0; j < 4; j++) \
    _Pragma("unroll") for (int f = 0; f < 4; f++) acc[i][j][f] = 0.f;

// ---------------- A = q~ @ k~^T (causal); qt/kt paired in n ----------------
__global__ __launch_bounds__(256, 2) void gemm_A(
    const uint32_t* __restrict__ qt, const uint32_t* __restrict__ kt,
    uint32_t* __restrict__ Am)
{
    extern __shared__ uint32_t dynsm[];
    uint32_t* SA = dynsm;
    uint32_t* SB = dynsm + NST2 * SZM;
    int bx = blockIdx.x, tid = threadIdx.x;

    float acc[4][4][4];
    ZERO_ACC(acc)

    pipe32<DK, 1, 1, DK, DK, true, true>(
        qt + (long)bx * CHK * DK, kt + (long)bx * CHK * DK,
        0, 0, tid, acc, SA, SB);
    epilogue<CHK, true, true>(acc, Am + (long)bx * CHK * CHK, 0, 0, tid);
}

// ---------------- U = V^T @ k~ (both KR, unchanged; U cols inherit pairing) ----------------
__global__ __launch_bounds__(256, 2) void gemm_U(
    const uint32_t* __restrict__ kt, const uint32_t* __restrict__ v,
    float* __restrict__ U)
{
    extern __shared__ uint32_t dynsm[];
    uint32_t* SA = dynsm;
    uint32_t* SB = dynsm + NST2 * SZM;
    int q = blockIdx.x, tid = threadIdx.x;
    int mt = q & 3, zz = q >> 2;
    int cz = zz >> 3, bb = zz & 7;

    float acc[4][4][4];
    ZERO_ACC(acc)

    pipe32<1, (long)B_DIM * DV, DK, 1, CHK, false, false>(
        v + (long)cz * CHK * B_DIM * DV + (long)bb * DV,
        kt + (long)zz * CHK * DK, mt * BM, 0, tid, acc, SA, SB);
    epilogue<DK, false, false>(acc, U + (long)zz * DV * DK, mt * BM, 0, tid);
}

// ---------------- fused Y: y = A@V + q~@S^T ----------------
__global__ __launch_bounds__(256, 2) void gemm_Y(
    const uint32_t* __restrict__ Am, const uint32_t* __restrict__ v,
    float* __restrict__ y, const uint32_t* __restrict__ qt,
    const uint32_t* __restrict__ S)
{
    extern __shared__ uint32_t dynsm[];
    uint32_t* SA = dynsm;
    uint32_t* SB = dynsm + NST2 * SZM;

    int bz = blockIdx.z;
    int cz = bz >> 3, bb = bz & 7;
    int n0 = blockIdx.x * BN;
    int tid = threadIdx.x;

    float acc[4][4][4];
    ZERO_ACC(acc)

    // phase 1: Am plain-KC, v KR
    pipe32<CHK, 1, (long)B_DIM * DV, 1, CHK, false, false>(
        Am + (long)bz * CHK * CHK,
        v + (long)cz * CHK * B_DIM * DV + (long)bb * DV,
        0, n0, tid, acc, SA, SB);
    // phase 2: qt paired-KC, S paired-KC
    pipe32<DK, 1, 1, DK, DK, true, true>(
        qt + (long)bz * CHK * DK,
        S + (long)bz * DV * DK,
        0, n0, tid, acc, SA, SB);

    epilogue<(long)B_DIM * DV, false, false>(
        acc, y + (long)cz * CHK * B_DIM * DV + (long)bb * DV, 0, n0, tid);
}

// ---------------- projection kernel: A = x (plain KC via LDG+cvt), B = W (paired KC) ----------------
struct ProjArgs {
    const float* X;
    const uint32_t* Bm[7];
    const float* biasm[7];
    void* Cm[7];
    int noff[7]; int cs[7]; int otf[7];
    int base;
};

__global__ __launch_bounds__(256, 2) void proj_kernel(ProjArgs g) {
    extern __shared__ uint32_t dynsm[];
    uint32_t* SA = dynsm;
    uint32_t* SB = dynsm + NST2 * SZ2;

    int sx = blockIdx.x + g.base;
    int m0 = blockIdx.y * BM;
    int n0 = g.noff[sx];
    int tid = threadIdx.x;
    constexpr int NKI = IN_D / BKT2;

    int warp = tid >> 5, lane = tid & 31;
    int wm0 = (warp & 1) * 64, wn0 = (warp >> 1) * 32;
    int gid = lane >> 2, tig = lane & 3;

    const float* __restrict__ X = g.X;
    const uint32_t* __restrict__ W = g.Bm[sx];

    float acc[4][4][4];
    ZERO_ACC(acc)

    float4 ra[4];
    auto ldgA = [&](int k0) {
#pragma unroll
        for (int i = 0; i < 4; i++) {
            int q = tid + i * 256;
            int r = q >> 3, c = q & 7;
            ra[i] = *reinterpret_cast<const float4*>(X + (long)(m0 + r) * IN_D + k0 + (c << 2));
        }
    };
    auto stsA = [&](uint32_t* dst) {
#pragma unroll
        for (int i = 0; i < 4; i++) {
            int q = tid + i * 256;
            int r = q >> 3, c = q & 7;
            uint4 o;
            o.x = f2tf32(ra[i].x); o.y = f2tf32(ra[i].y);
            o.z = f2tf32(ra[i].z); o.w = f2tf32(ra[i].w);
            *reinterpret_cast<uint4*>(dst + kc32_off(r, c << 2)) = o;
        }
    };
    auto issueB = [&](uint32_t* dst, int k0) {
#pragma unroll
        for (int i = 0; i < 4; i++) {
            int q = tid + i * 256;
            int r = q >> 3, c = q & 7;
            cp16(dst + kp32_off(r, c << 2), W + (long)(n0 + r) * IN_D + (k0 + (c << 2)));
        }
    };

    ldgA(0);
    stsA(SA);
    ldgA(BKT2);
    issueB(SB, 0);          cp_commit();
    issueB(SB + SZ2, BKT2); cp_commit();

    int stage = 0;
    for (int i = 0; i < NKI; i++) {
        cp_wait1();
        __syncthreads();
        {
            int s1 = stage + 1; if (s1 >= NST2) s1 -= NST2;
            int s2s = stage + 2; if (s2s >= NST2) s2s -= NST2;
            if (i + 2 < NKI) issueB(SB + s2s * SZ2, (i + 2) * BKT2);
            cp_commit();
            if (i + 1 < NKI) stsA(SA + s1 * SZ2);
            if (i + 2 < NKI) ldgA((i + 2) * BKT2);
        }
        const uint32_t* sa = SA + stage * SZ2;
        const uint32_t* sb = SB + stage * SZ2;
#pragma unroll
        for (int ks = 0; ks < BKT2; ks += 8) {
            uint32_t af[4][4], bf2[4][2];
#pragma unroll
            for (int mi = 0; mi < 4; mi++) {
                int mr = wm0 + mi * 16 + gid;
                int fm = (mr & 7) << 2;
                const uint32_t* r0p = sa + (mr << 5);
                const uint32_t* r1p = sa + ((mr + 8) << 5);
                af[mi][0] = r0p[(ks + tig) ^ fm];
                af[mi][1] = r1p[(ks + tig) ^ fm];
                af[mi][2] = r0p[(ks + tig + 4) ^ fm];
                af[mi][3] = r1p[(ks + tig + 4) ^ fm];
            }
#pragma unroll
            for (int ni = 0; ni < 4; ni++) {
                int nc = wn0 + ni * 8 + gid;
                uint2 p = *reinterpret_cast<const uint2*>(
                    sb + (nc << 5) + ((ks + tig * 2) ^ ((nc & 3) << 3)));
                bf2[ni][0] = p.x; bf2[ni][1] = p.y;
            }
#pragma unroll
            for (int mi = 0; mi < 4; mi++)
#pragma unroll
                for (int ni = 0; ni < 4; ni++)
                    mma_tf32(acc[mi][ni], af[mi], bf2[ni]);
        }
        stage++; if (stage == NST2) stage = 0;
    }

    const float* bias = g.biasm[sx];
    int cs = g.cs[sx];
    int otf = g.otf[sx];
#pragma unroll
    for (int mi = 0; mi < 4; mi++) {
        int r0 = m0 + wm0 + mi * 16 + gid;
#pragma unroll
        for (int ni = 0; ni < 4; ni++) {
            int c0 = n0 + wn0 + ni * 8 + 2 * tig;
#pragma unroll
            for (int f = 0; f < 4; f++) {
                int row = r0 + (f >> 1) * 8;
                int col = c0 + (f & 1);
                float v = acc[mi][ni][f] + bias[col];
                long idx = (long)row * cs + col;
                if (otf) ((uint32_t*)g.Cm[sx])[idx] = f2tf32(v);
                else     ((float*)g.Cm[sx])[idx]    = v;
            }
        }
    }
}

// ---------------- weight conversion: gather into PAIRED-k order ----------------
#define NW4 ((DV + 3*DK) * IN_D / 4)
__global__ void conv_w(const float* __restrict__ wv, const float* __restrict__ wk,
                       const float* __restrict__ wq, const float* __restrict__ wa)
{
    long i = (long)blockIdx.x * blockDim.x + threadIdx.x;   // output uint4 index
    if (i >= NW4) return;
    const long NWVW = (long)DV * IN_D, NWKW = (long)DK * IN_D;
    long base = i << 2;                  // paired-space word index
    long rowbase = base & ~511;          // IN_D=512 words per row (base%512 within row)
    int p0 = (int)(base & 511);          // paired pos of first word (16B aligned)
    uint4 o;
    uint32_t* out = (uint32_t*)&o;
#pragma unroll
    for (int j = 0; j < 4; j++) {
        int p = p0 + j;
        int k = (p & ~7) | ((p >> 1) & 3) | ((p & 1) << 2);   // unpair
        long src = rowbase + k;
        float s;
        if (src < NWVW) s = wv[src];
        else { long t = src - NWVW;
            if (t < NWKW) s = wk[t];
            else { t -= NWKW;
                if (t < NWKW) s = wq[t];
                else s = wa[t - NWKW];
            }
        }
        out[j] = f2tf32(s);
    }
    ((uint4*)g_wt)[i] = o;
}

// ---------------- parallel decay prep: outputs at PAIRED n positions ----------------
#define NSEG 8
#define SEGL (CHK / NSEG)
#define NHALF 64
__global__ __launch_bounds__(512) void prep_kernel() {
    int blk = blockIdx.x;
    int cb = blk >> 1, half = blk & 1;
    int c = cb >> 3, b = cb & 7;
    int tid = threadIdx.x;
    int n = half * NHALF + (tid & (NHALF - 1));
    int seg = tid >> 6;
    int np = PPAIR(n);

    __shared__ float sprod[NSEG][NHALF];

    int t0 = seg * SEGL;
    float sg[SEGL];
    float p = 1.f;
#pragma unroll
    for (int i = 0; i < SEGL; i++) {
        long row = (long)(c * CHK + t0 + i) * B_DIM + b;
        float av = g_a[row * DK + n];
        float s = fmaxf(__fdividef(1.f, 1.f + __expf(-av)), EPSV);
        sg[i] = s;
        p *= s;
    }
    sprod[seg][tid & (NHALF - 1)] = p;
    __syncthreads();

    float cp = 1.f;
#pragma unroll
    for (int j = 0; j < NSEG - 1; j++)
        if (j < seg) cp *= sprod[j][tid & (NHALF - 1)];

    long base_o = ((long)cb * CHK) * DK + np;
#pragma unroll
    for (int i = 0; i < SEGL; i++) {
        int t = t0 + i;
        long row = (long)(c * CHK + t) * B_DIM + b;
        cp *= sg[i];
        g_qt[base_o + (long)t * DK] = f2tf32(g_q[row * DK + n] * cp);
        g_kt[base_o + (long)t * DK] = f2tf32(g_k[row * DK + n] / (cp + EPSV));
    }
    if (seg == NSEG - 1)
        g_cpl[(long)cb * DK + np] = cp;
}

// ---------------- inter-chunk state scan (n-oblivious: memory order consistent) ----------------
__global__ void scan_kernel() {
    int id = blockIdx.x * blockDim.x + threadIdx.x;
    int n = id & (DK - 1);
    int d = (id >> 7) & (DV - 1);
    int b = id >> 16;
    float s = 0.f;
#pragma unroll
    for (int c = 0; c < NCH; c++) {
        long off = (((long)c * B_DIM + b) * DV + d) * DK + n;
        g_S[off] = f2tf32(s);
        float cl = g_cpl[((long)c * B_DIM + b) * DK + n];
        s = cl * (s + g_U[off]);
    }
}

// ---------------- host launcher ----------------
extern "C" void kernel_launch(void* const* d_in, const int* in_sizes, int n_in,
                              void* d_out, int out_size) {
    const float* x  = (const float*)d_in[0];
    const float* Wv = (const float*)d_in[1];
    const float* bv = (const float*)d_in[2];
    const float* Wk = (const float*)d_in[3];
    const float* bk = (const float*)d_in[4];
    const float* Wq = (const float*)d_in[5];
    const float* bq = (const float*)d_in[6];
    const float* Wa = (const float*)d_in[7];
    const float* ba = (const float*)d_in[8];
    float* y = (float*)d_out;
    (void)in_sizes; (void)n_in; (void)out_size;

    uint32_t *pwt, *pv, *pqt, *pkt, *pA, *pS;
    float *pk, *pq, *pa, *pU;
    cudaGetSymbolAddress((void**)&pwt, g_wt);
    cudaGetSymbolAddress((void**)&pv,  g_v);
    cudaGetSymbolAddress((void**)&pk,  g_k);
    cudaGetSymbolAddress((void**)&pq,  g_q);
    cudaGetSymbolAddress((void**)&pa,  g_a);
    cudaGetSymbolAddress((void**)&pqt, g_qt);
    cudaGetSymbolAddress((void**)&pkt, g_kt);
    cudaGetSymbolAddress((void**)&pA,  g_Am);
    cudaGetSymbolAddress((void**)&pU,  g_U);
    cudaGetSymbolAddress((void**)&pS,  g_S);

    static cudaStream_t s2 = 0;
    static cudaEvent_t evW = 0, evP = 0, evS = 0;
    static bool inited = false;
    if (!inited) {
        cudaStreamCreateWithFlags(&s2, cudaStreamNonBlocking);
        cudaEventCreateWithFlags(&evW, cudaEventDisableTiming);
        cudaEventCreateWithFlags(&evP, cudaEventDisableTiming);
        cudaEventCreateWithFlags(&evS, cudaEventDisableTiming);
        cudaFuncSetAttribute(proj_kernel, cudaFuncAttributeMaxDynamicSharedMemorySize, DYN2);
        cudaFuncSetAttribute(gemm_A, cudaFuncAttributeMaxDynamicSharedMemorySize, DYNM);
        cudaFuncSetAttribute(gemm_U, cudaFuncAttributeMaxDynamicSharedMemorySize, DYNM);
        cudaFuncSetAttribute(gemm_Y, cudaFuncAttributeMaxDynamicSharedMemorySize, DYNM);
        inited = true;
    }

    // ---- weight tf32 conversion into paired-k order ----
    conv_w<<<(NW4 + 255) / 256, 256>>>(Wv, Wk, Wq, Wa);

    // fork
    cudaEventRecord(evW, 0);
    cudaStreamWaitEvent(s2, evW, 0);

    ProjArgs gp;
    {
        gp.X = x;
        const long NWV4 = DV * IN_D / 4, NWK4 = DK * IN_D / 4;
        const uint32_t* wv_t = pwt;
        const uint32_t* wk_t = pwt + NWV4 * 4;
        const uint32_t* wq_t = pwt + (NWV4 + NWK4) * 4;
        const uint32_t* wa_t = pwt + (NWV4 + 2 * NWK4) * 4;
        const uint32_t* Bm[7]    = {wk_t, wq_t, wa_t, wv_t, wv_t, wv_t, wv_t};
        const float*    biasm[7] = {bk, bq, ba, bv, bv, bv, bv};
        void*           Cm[7]    = {pk, pq, pa, pv, pv, pv, pv};
        int             noff[7]  = {0, 0, 0, 0, 128, 256, 384};
        int             cs[7]    = {DK, DK, DK, DV, DV, DV, DV};
        int             otf[7]   = {0, 0, 0, 1, 1, 1, 1};
        for (int i = 0; i < 7; i++) {
            gp.Bm[i] = Bm[i]; gp.biasm[i] = biasm[i]; gp.Cm[i] = Cm[i];
            gp.noff[i] = noff[i]; gp.cs[i] = cs[i]; gp.otf[i] = otf[i];
        }
    }

    gp.base = 0;
    proj_kernel<<<dim3(3, T_DIM * B_DIM / BM, 1), 256, DYN2, 0>>>(gp);
    ProjArgs gpv = gp; gpv.base = 3;
    proj_kernel<<<dim3(4, T_DIM * B_DIM / BM, 1), 256, DYN2, s2>>>(gpv);

    prep_kernel<<<NCH * B_DIM * 2, 512, 0, 0>>>();
    cudaEventRecord(evP, 0);
    gemm_A<<<NCH * B_DIM, 256, DYNM, 0>>>(pqt, pkt, pA);

    cudaStreamWaitEvent(s2, evP, 0);
    gemm_U<<<NCH * B_DIM * (DV / BM), 256, DYNM, s2>>>(pkt, pv, pU);
    scan_kernel<<<(B_DIM * DV * DK) / 256, 256, 0, s2>>>();
    cudaEventRecord(evS, s2);

    cudaStreamWaitEvent(0, evS, 0);
    gemm_Y<<<dim3(DV / BN, 1, NCH * B_DIM), 256, DYNM, 0>>>(pA, pv, y, pqt, pS);
}